// round 1
// baseline (speedup 1.0000x reference)
#include <cuda_runtime.h>
#include <math.h>
#include <stdint.h>

// Problem constants (fixed by setup_inputs)
#define TOK   32768          // B*N = 8*4096
#define NEXP  8
#define DDIM  512
#define BND   16777216       // TOK * DDIM
#define LN_EPS 1e-5f

// ---------------------------------------------------------------------------
// Scratch (no allocations allowed -> __device__ globals)
// ---------------------------------------------------------------------------
__device__ int   g_cnt[NEXP];                       // per-expert routed count
__device__ int   g_pairTok[NEXP * TOK];             // pair slot -> token id
__device__ int   g_tokPair[TOK * 4];                // token -> 4 pair indices
__device__ float g_tokW[TOK * 4];                   // token -> 4 weights
__device__ float g_h1[(size_t)NEXP * TOK * DDIM];   // GEMM1 out / LN1 in-place
__device__ float g_h2[(size_t)NEXP * TOK * DDIM];   // GEMM2 out / LN2 in-place
__device__ float g_part[4096];                      // combine-block diff^2 partials

// ---------------------------------------------------------------------------
// 0) zero counters (graph replays re-run this)
// ---------------------------------------------------------------------------
__global__ void init_kernel() {
    if (threadIdx.x < NEXP) g_cnt[threadIdx.x] = 0;
}

// ---------------------------------------------------------------------------
// 1) gating: warp per token. scores = x @ Wg + bg, top2 & bottom2, softmax
// ---------------------------------------------------------------------------
__global__ void gating_kernel(const float* __restrict__ x,
                              const float* __restrict__ Wg,
                              const float* __restrict__ bg) {
    int gw = (blockIdx.x * blockDim.x + threadIdx.x) >> 5;
    if (gw >= TOK) return;
    int lane = threadIdx.x & 31;
    const float* xr = x + (size_t)gw * DDIM;

    float s[NEXP];
#pragma unroll
    for (int e = 0; e < NEXP; e++) s[e] = 0.f;

    for (int d = lane; d < DDIM; d += 32) {
        float xv = xr[d];
        const float* wr = Wg + d * NEXP;
#pragma unroll
        for (int e = 0; e < NEXP; e++) s[e] += xv * wr[e];
    }
#pragma unroll
    for (int e = 0; e < NEXP; e++) {
#pragma unroll
        for (int o = 16; o > 0; o >>= 1)
            s[e] += __shfl_xor_sync(0xffffffffu, s[e], o);
    }

    if (lane == 0) {
#pragma unroll
        for (int e = 0; e < NEXP; e++) s[e] += bg[e];

        // top-2 (largest)
        int i0 = 0; float v0 = s[0];
        for (int e = 1; e < NEXP; e++) if (s[e] > v0) { v0 = s[e]; i0 = e; }
        int i1 = -1; float v1 = -1e30f;
        for (int e = 0; e < NEXP; e++) if (e != i0 && s[e] > v1) { v1 = s[e]; i1 = e; }
        // bottom-2 (smallest)
        int j0 = 0; float u0 = s[0];
        for (int e = 1; e < NEXP; e++) if (s[e] < u0) { u0 = s[e]; j0 = e; }
        int j1 = -1; float u1 = 1e30f;
        for (int e = 0; e < NEXP; e++) if (e != j0 && s[e] < u1) { u1 = s[e]; j1 = e; }

        // softmax over (v0, v1), v0 >= v1
        float et  = expf(v1 - v0);
        float wt0 = 1.f / (1.f + et);
        float wt1 = et * wt0;
        // softmax over (u0, u1), u1 >= u0
        float eb  = expf(u0 - u1);
        float wb1 = 1.f / (1.f + eb);
        float wb0 = eb * wb1;

        int p;
        p = atomicAdd(&g_cnt[i0], 1);
        g_pairTok[i0 * TOK + p] = gw;
        g_tokPair[gw * 4 + 0] = i0 * TOK + p;  g_tokW[gw * 4 + 0] = wt0;
        p = atomicAdd(&g_cnt[i1], 1);
        g_pairTok[i1 * TOK + p] = gw;
        g_tokPair[gw * 4 + 1] = i1 * TOK + p;  g_tokW[gw * 4 + 1] = wt1;
        p = atomicAdd(&g_cnt[j0], 1);
        g_pairTok[j0 * TOK + p] = gw;
        g_tokPair[gw * 4 + 2] = j0 * TOK + p;  g_tokW[gw * 4 + 2] = wb0;
        p = atomicAdd(&g_cnt[j1], 1);
        g_pairTok[j1 * TOK + p] = gw;
        g_tokPair[gw * 4 + 3] = j1 * TOK + p;  g_tokW[gw * 4 + 3] = wb1;
    }
}

// ---------------------------------------------------------------------------
// 2/4) tiled fp32 GEMM: C[r, n] = A[r, :] @ W[e][:, n] + bias[e][n]
//      GATHER=true : A rows gathered from x by token id, out = g_h1
//      GATHER=false: A rows = g_h1 (contiguous per expert),  out = g_h2
//      BM=BN=128, BK=16, 256 threads, 8x8 per thread
// ---------------------------------------------------------------------------
template <bool GATHER>
__global__ void __launch_bounds__(256, 2) gemm_kernel(
    const float* __restrict__ Xsrc,
    const float* __restrict__ W,
    const float* __restrict__ bias)
{
    const int e   = blockIdx.z;
    const int cnt = g_cnt[e];
    const int m0  = blockIdx.y * 128;
    if (m0 >= cnt) return;
    const int n0  = blockIdx.x * 128;

    __shared__ __align__(16) float As[16][132];
    __shared__ __align__(16) float Bs[16][128];
    __shared__ const float* Arow[128];

    const int tid = threadIdx.x;
    for (int i = tid; i < 128; i += 256) {
        int r = m0 + i; if (r > cnt - 1) r = cnt - 1;
        const float* p;
        if (GATHER) p = Xsrc + (size_t)g_pairTok[e * TOK + r] * DDIM;
        else        p = g_h1 + ((size_t)e * TOK + r) * DDIM;
        Arow[i] = p;
    }
    __syncthreads();

    const int ar = tid >> 1;
    const int ak = (tid & 1) * 8;
    const float* aptr = Arow[ar] + ak;
    const int bk = tid >> 4;
    const int bn = (tid & 15) * 8;
    const float* bptr = W + ((size_t)e * DDIM + bk) * DDIM + n0 + bn;

    const int ty = (tid >> 4) * 8;
    const int tx = (tid & 15) * 8;

    float acc[8][8];
#pragma unroll
    for (int i = 0; i < 8; i++)
#pragma unroll
        for (int j = 0; j < 8; j++) acc[i][j] = 0.f;

    for (int k0 = 0; k0 < DDIM; k0 += 16) {
        float4 a0 = *(const float4*)(aptr + k0);
        float4 a1 = *(const float4*)(aptr + k0 + 4);
        float4 b0 = *(const float4*)(bptr + (size_t)k0 * DDIM);
        float4 b1 = *(const float4*)(bptr + (size_t)k0 * DDIM + 4);
        __syncthreads();
        As[ak + 0][ar] = a0.x; As[ak + 1][ar] = a0.y;
        As[ak + 2][ar] = a0.z; As[ak + 3][ar] = a0.w;
        As[ak + 4][ar] = a1.x; As[ak + 5][ar] = a1.y;
        As[ak + 6][ar] = a1.z; As[ak + 7][ar] = a1.w;
        *(float4*)&Bs[bk][bn]     = b0;
        *(float4*)&Bs[bk][bn + 4] = b1;
        __syncthreads();
#pragma unroll
        for (int kk = 0; kk < 16; kk++) {
            float4 A03 = *(const float4*)&As[kk][ty];
            float4 A47 = *(const float4*)&As[kk][ty + 4];
            float4 B03 = *(const float4*)&Bs[kk][tx];
            float4 B47 = *(const float4*)&Bs[kk][tx + 4];
            float a[8] = {A03.x, A03.y, A03.z, A03.w, A47.x, A47.y, A47.z, A47.w};
            float b[8] = {B03.x, B03.y, B03.z, B03.w, B47.x, B47.y, B47.z, B47.w};
#pragma unroll
            for (int i = 0; i < 8; i++)
#pragma unroll
                for (int j = 0; j < 8; j++)
                    acc[i][j] += a[i] * b[j];
        }
    }

    float4 bb0 = *(const float4*)(bias + e * DDIM + n0 + tx);
    float4 bb1 = *(const float4*)(bias + e * DDIM + n0 + tx + 4);
    float bv[8] = {bb0.x, bb0.y, bb0.z, bb0.w, bb1.x, bb1.y, bb1.z, bb1.w};

    float* OutB = GATHER ? g_h1 : g_h2;
#pragma unroll
    for (int i = 0; i < 8; i++) {
        int r = m0 + ty + i;
        if (r < cnt) {
            float* o = OutB + ((size_t)e * TOK + r) * DDIM + n0 + tx;
            float4 o0 = make_float4(acc[i][0] + bv[0], acc[i][1] + bv[1],
                                    acc[i][2] + bv[2], acc[i][3] + bv[3]);
            float4 o1 = make_float4(acc[i][4] + bv[4], acc[i][5] + bv[5],
                                    acc[i][6] + bv[6], acc[i][7] + bv[7]);
            *(float4*)o       = o0;
            *(float4*)(o + 4) = o1;
        }
    }
}

// ---------------------------------------------------------------------------
// 3/5) LayerNorm (warp per row, in place). WHICH=1: g_h1 + relu; WHICH=2: g_h2
// ---------------------------------------------------------------------------
template <int WHICH>
__global__ void ln_kernel(const float* __restrict__ w,
                          const float* __restrict__ b) {
    int gw = (blockIdx.x * blockDim.x + threadIdx.x) >> 5;
    int e   = gw >> 15;          // / TOK
    int pos = gw & (TOK - 1);
    if (pos >= g_cnt[e]) return;
    int lane = threadIdx.x & 31;
    float* row = (WHICH == 1 ? g_h1 : g_h2) + (size_t)gw * DDIM;

    float v[16];
    float s = 0.f;
#pragma unroll
    for (int i = 0; i < 16; i++) { v[i] = row[lane + i * 32]; s += v[i]; }
#pragma unroll
    for (int o = 16; o > 0; o >>= 1) s += __shfl_xor_sync(0xffffffffu, s, o);
    float mu = s * (1.f / DDIM);

    float q = 0.f;
#pragma unroll
    for (int i = 0; i < 16; i++) { float d = v[i] - mu; q += d * d; }
#pragma unroll
    for (int o = 16; o > 0; o >>= 1) q += __shfl_xor_sync(0xffffffffu, q, o);
    float rstd = rsqrtf(q * (1.f / DDIM) + LN_EPS);

    const float* we = w + e * DDIM;
    const float* be = b + e * DDIM;
#pragma unroll
    for (int i = 0; i < 16; i++) {
        int d = lane + i * 32;
        float y = (v[i] - mu) * rstd * we[d] + be[d];
        if (WHICH == 1) y = fmaxf(y, 0.f);
        row[d] = y;
    }
}

// ---------------------------------------------------------------------------
// 6) combine: warp per token -> out_top/out_bot/output + diff^2 partials
// ---------------------------------------------------------------------------
__global__ void combine_kernel(const float* __restrict__ x,
                               float* __restrict__ out) {
    int gw   = (blockIdx.x * blockDim.x + threadIdx.x) >> 5;  // token
    int lane = threadIdx.x & 31;
    const int t = gw;

    int   p0 = g_tokPair[t * 4 + 0], p1 = g_tokPair[t * 4 + 1];
    int   p2 = g_tokPair[t * 4 + 2], p3 = g_tokPair[t * 4 + 3];
    float w0 = g_tokW[t * 4 + 0], w1 = g_tokW[t * 4 + 1];
    float w2 = g_tokW[t * 4 + 2], w3 = g_tokW[t * 4 + 3];

    const float* ha = g_h2 + (size_t)p0 * DDIM;
    const float* hb = g_h2 + (size_t)p1 * DDIM;
    const float* hc = g_h2 + (size_t)p2 * DDIM;
    const float* hd = g_h2 + (size_t)p3 * DDIM;
    const float* xr = x + (size_t)t * DDIM;
    float* o_out = out + (size_t)t * DDIM;
    float* o_top = out + (size_t)BND + (size_t)t * DDIM;
    float* o_bot = out + 2 * (size_t)BND + (size_t)t * DDIM;

    float accd = 0.f;
#pragma unroll
    for (int i = 0; i < 16; i++) {
        int d = lane + i * 32;
        float top = w0 * ha[d] + w1 * hb[d];
        float bot = w2 * hc[d] + w3 * hd[d];
        o_top[d] = top;
        o_bot[d] = bot;
        o_out[d] = top + xr[d];
        float df = top - bot;
        accd += df * df;
    }
#pragma unroll
    for (int o = 16; o > 0; o >>= 1) accd += __shfl_xor_sync(0xffffffffu, accd, o);

    __shared__ float red[8];
    if (lane == 0) red[threadIdx.x >> 5] = accd;
    __syncthreads();
    if (threadIdx.x == 0) {
        float ssum = 0.f;
        for (int i = 0; i < 8; i++) ssum += red[i];
        g_part[blockIdx.x] = ssum;   // 512 blocks per batch, fixed order
    }
}

// ---------------------------------------------------------------------------
// 7) loss: deterministic fixed-order reduction, 1 block
// ---------------------------------------------------------------------------
__global__ void loss_kernel(float* __restrict__ out) {
    int w = threadIdx.x >> 5, lane = threadIdx.x & 31;
    __shared__ float lred[8];
    float s = 0.f;
    for (int i = lane; i < 512; i += 32) s += g_part[w * 512 + i];
#pragma unroll
    for (int o = 16; o > 0; o >>= 1) s += __shfl_xor_sync(0xffffffffu, s, o);
    if (lane == 0) lred[w] = 1.f / (sqrtf(s) + 1e-8f);
    __syncthreads();
    if (threadIdx.x == 0) {
        float a = 0.f;
        for (int i = 0; i < 8; i++) a += lred[i];
        out[(size_t)3 * BND] = a * (1.f / 8.f);
    }
}

// ---------------------------------------------------------------------------
// launch
// ---------------------------------------------------------------------------
extern "C" void kernel_launch(void* const* d_in, const int* in_sizes, int n_in,
                              void* d_out, int out_size) {
    const float* x    = (const float*)d_in[0];
    const float* Wg   = (const float*)d_in[1];
    const float* bg   = (const float*)d_in[2];
    const float* W1   = (const float*)d_in[3];
    const float* b1   = (const float*)d_in[4];
    const float* ln1w = (const float*)d_in[5];
    const float* ln1b = (const float*)d_in[6];
    const float* W2   = (const float*)d_in[7];
    const float* b2   = (const float*)d_in[8];
    const float* ln2w = (const float*)d_in[9];
    const float* ln2b = (const float*)d_in[10];
    float* out = (float*)d_out;

    init_kernel<<<1, 32>>>();
    gating_kernel<<<TOK * 32 / 256, 256>>>(x, Wg, bg);

    dim3 ggrid(DDIM / 128, TOK / 128, NEXP);   // (4, 256, 8)
    gemm_kernel<true><<<ggrid, 256>>>(x, W1, b1);
    ln_kernel<1><<<NEXP * TOK * 32 / 256, 256>>>(ln1w, ln1b);
    gemm_kernel<false><<<ggrid, 256>>>(nullptr, W2, b2);
    ln_kernel<2><<<NEXP * TOK * 32 / 256, 256>>>(ln2w, ln2b);

    combine_kernel<<<TOK * 32 / 256, 256>>>(x, out);
    loss_kernel<<<1, 256>>>(out);
}

// round 3
// speedup vs baseline: 1.4090x; 1.4090x over previous
#include <cuda_runtime.h>
#include <cuda_bf16.h>
#include <math.h>
#include <stdint.h>

// Problem constants
#define TOK   32768          // B*N = 8*4096
#define NEXP  8
#define DDIM  512
#define BND   16777216       // TOK * DDIM
#define LN_EPS 1e-5f

// GEMM tile config (mma.sync path; tcgen05 unavailable at compute_103 base target)
#define BM 128
#define BN 128
#define BK 32
#define NCHUNK (DDIM / BK)   // 16
#define ASTRIDE 40           // bf16 elems per smem row (80B, conflict-free ldmatrix)

// ---------------------------------------------------------------------------
// Scratch (__device__ globals; no allocations allowed)
// ---------------------------------------------------------------------------
__device__ int   g_cnt[NEXP];
__device__ int   g_pairTok[NEXP * TOK];
__device__ int   g_tokPair[TOK * 4];
__device__ float g_tokW[TOK * 4];
__device__ float g_h1[(size_t)NEXP * TOK * DDIM];
__device__ float g_h2[(size_t)NEXP * TOK * DDIM];
__device__ float g_part[4096];
__device__ __nv_bfloat16 g_w1t_hi[(size_t)NEXP * DDIM * DDIM];
__device__ __nv_bfloat16 g_w1t_lo[(size_t)NEXP * DDIM * DDIM];
__device__ __nv_bfloat16 g_w2t_hi[(size_t)NEXP * DDIM * DDIM];
__device__ __nv_bfloat16 g_w2t_lo[(size_t)NEXP * DDIM * DDIM];

// ---------------------------------------------------------------------------
// Helpers
// ---------------------------------------------------------------------------
__device__ __forceinline__ uint32_t smem_u32(const void* p) {
    uint32_t a;
    asm("{ .reg .u64 t; cvta.to.shared.u64 t, %1; cvt.u32.u64 %0, t; }" : "=r"(a) : "l"(p));
    return a;
}
__device__ __forceinline__ void ldsm4(uint32_t* r, uint32_t addr) {
    asm volatile("ldmatrix.sync.aligned.m8n8.x4.shared.b16 {%0,%1,%2,%3}, [%4];"
                 : "=r"(r[0]), "=r"(r[1]), "=r"(r[2]), "=r"(r[3]) : "r"(addr));
}
__device__ __forceinline__ void ldsm2(uint32_t* r, uint32_t addr) {
    asm volatile("ldmatrix.sync.aligned.m8n8.x2.shared.b16 {%0,%1}, [%2];"
                 : "=r"(r[0]), "=r"(r[1]) : "r"(addr));
}
__device__ __forceinline__ void mma16816(float* c, const uint32_t* a, const uint32_t* b) {
    asm volatile(
        "mma.sync.aligned.m16n8k16.row.col.f32.bf16.bf16.f32 "
        "{%0,%1,%2,%3}, {%4,%5,%6,%7}, {%8,%9}, {%0,%1,%2,%3};"
        : "+f"(c[0]), "+f"(c[1]), "+f"(c[2]), "+f"(c[3])
        : "r"(a[0]), "r"(a[1]), "r"(a[2]), "r"(a[3]), "r"(b[0]), "r"(b[1]));
}

// ---------------------------------------------------------------------------
// 0) zero counters
// ---------------------------------------------------------------------------
__global__ void init_kernel() {
    if (threadIdx.x < NEXP) g_cnt[threadIdx.x] = 0;
}

// ---------------------------------------------------------------------------
// 1) gating
// ---------------------------------------------------------------------------
__global__ void gating_kernel(const float* __restrict__ x,
                              const float* __restrict__ Wg,
                              const float* __restrict__ bg) {
    int gw = (blockIdx.x * blockDim.x + threadIdx.x) >> 5;
    if (gw >= TOK) return;
    int lane = threadIdx.x & 31;
    const float* xr = x + (size_t)gw * DDIM;

    float s[NEXP];
#pragma unroll
    for (int e = 0; e < NEXP; e++) s[e] = 0.f;
    for (int d = lane; d < DDIM; d += 32) {
        float xv = xr[d];
        const float* wr = Wg + d * NEXP;
#pragma unroll
        for (int e = 0; e < NEXP; e++) s[e] += xv * wr[e];
    }
#pragma unroll
    for (int e = 0; e < NEXP; e++) {
#pragma unroll
        for (int o = 16; o > 0; o >>= 1)
            s[e] += __shfl_xor_sync(0xffffffffu, s[e], o);
    }
    if (lane == 0) {
#pragma unroll
        for (int e = 0; e < NEXP; e++) s[e] += bg[e];
        int i0 = 0; float v0 = s[0];
        for (int e = 1; e < NEXP; e++) if (s[e] > v0) { v0 = s[e]; i0 = e; }
        int i1 = -1; float v1 = -1e30f;
        for (int e = 0; e < NEXP; e++) if (e != i0 && s[e] > v1) { v1 = s[e]; i1 = e; }
        int j0 = 0; float u0 = s[0];
        for (int e = 1; e < NEXP; e++) if (s[e] < u0) { u0 = s[e]; j0 = e; }
        int j1 = -1; float u1 = 1e30f;
        for (int e = 0; e < NEXP; e++) if (e != j0 && s[e] < u1) { u1 = s[e]; j1 = e; }

        float et  = expf(v1 - v0);
        float wt0 = 1.f / (1.f + et);
        float wt1 = et * wt0;
        float eb  = expf(u0 - u1);
        float wb1 = 1.f / (1.f + eb);
        float wb0 = eb * wb1;

        int p;
        p = atomicAdd(&g_cnt[i0], 1);
        g_pairTok[i0 * TOK + p] = gw;
        g_tokPair[gw * 4 + 0] = i0 * TOK + p;  g_tokW[gw * 4 + 0] = wt0;
        p = atomicAdd(&g_cnt[i1], 1);
        g_pairTok[i1 * TOK + p] = gw;
        g_tokPair[gw * 4 + 1] = i1 * TOK + p;  g_tokW[gw * 4 + 1] = wt1;
        p = atomicAdd(&g_cnt[j0], 1);
        g_pairTok[j0 * TOK + p] = gw;
        g_tokPair[gw * 4 + 2] = j0 * TOK + p;  g_tokW[gw * 4 + 2] = wb0;
        p = atomicAdd(&g_cnt[j1], 1);
        g_pairTok[j1 * TOK + p] = gw;
        g_tokPair[gw * 4 + 3] = j1 * TOK + p;  g_tokW[gw * 4 + 3] = wb1;
    }
}

// ---------------------------------------------------------------------------
// 1b) weight prep: W[e][k][n] fp32 -> Wt_hi/lo[e][n][k] bf16 (transpose + split)
// ---------------------------------------------------------------------------
template <int WHICH>
__global__ void wconv_kernel(const float* __restrict__ W) {
    __shared__ float t[32][33];
    int e  = blockIdx.z;
    int kb = blockIdx.x * 32, nb = blockIdx.y * 32;
    const float* src = W + (size_t)e * DDIM * DDIM;
    int tx = threadIdx.x, ty = threadIdx.y;
#pragma unroll
    for (int r = ty; r < 32; r += 8)
        t[r][tx] = src[(size_t)(kb + r) * DDIM + nb + tx];
    __syncthreads();
    __nv_bfloat16* Th = (WHICH == 1) ? g_w1t_hi : g_w2t_hi;
    __nv_bfloat16* Tl = (WHICH == 1) ? g_w1t_lo : g_w2t_lo;
#pragma unroll
    for (int r = ty; r < 32; r += 8) {
        float v = t[tx][r];  // = W[kb+tx][nb+r]
        __nv_bfloat16 h = __float2bfloat16(v);
        __nv_bfloat16 l = __float2bfloat16(v - __bfloat162float(h));
        size_t o = ((size_t)e * DDIM + (nb + r)) * DDIM + kb + tx;
        Th[o] = h;
        Tl[o] = l;
    }
}

// ---------------------------------------------------------------------------
// 2/4) bf16x3 HMMA GEMM via mma.sync: C[r,:] = A[r,:] @ W[e] + bias[e]
//      BM=128, BN=128, BK=32; 256 threads = 8 warps (2 x 4), warp tile 64x32
// ---------------------------------------------------------------------------
template <bool GATHER>
__global__ void __launch_bounds__(256, 1) gemm_mma(const float* __restrict__ Xsrc,
                                                   const float* __restrict__ bias) {
    const int e   = blockIdx.z;
    const int cnt = g_cnt[e];
    const int m0  = blockIdx.y * BM;
    if (m0 >= cnt) return;
    const int n0  = blockIdx.x * BN;

    __shared__ __align__(16) __nv_bfloat16 sAh[BM][ASTRIDE];
    __shared__ __align__(16) __nv_bfloat16 sAl[BM][ASTRIDE];
    __shared__ __align__(16) __nv_bfloat16 sBh[BN][ASTRIDE];
    __shared__ __align__(16) __nv_bfloat16 sBl[BN][ASTRIDE];
    __shared__ const float* Arow[BM];

    const int tid  = threadIdx.x;
    const int wid  = tid >> 5;
    const int lane = tid & 31;

    for (int i = tid; i < BM; i += 256) {
        int r = m0 + i;
        if (r > cnt - 1) r = cnt - 1;
        Arow[i] = GATHER ? (Xsrc + (size_t)g_pairTok[e * TOK + r] * DDIM)
                         : (g_h1 + ((size_t)e * TOK + r) * DDIM);
    }
    __syncthreads();

    const __nv_bfloat16* wtH = GATHER ? g_w1t_hi : g_w2t_hi;
    const __nv_bfloat16* wtL = GATHER ? g_w1t_lo : g_w2t_lo;

    // loader assignment: row = tid>>1, half = (tid&1)*16
    const int lrow  = tid >> 1;
    const int lhalf = (tid & 1) * 16;
    const __nv_bfloat16* bHp = wtH + ((size_t)e * DDIM + n0 + lrow) * DDIM + lhalf;
    const __nv_bfloat16* bLp = wtL + ((size_t)e * DDIM + n0 + lrow) * DDIM + lhalf;

    // warp layout: warp_m = wid>>2 (64 rows), warp_n = wid&3 (32 cols)
    const int warp_m = wid >> 2;
    const int warp_n = wid & 3;

    // ldmatrix per-lane addresses (element offsets; x2 lanes 16-31 mirror 0-15)
    const int l15 = lane & 15;
    const uint32_t aAdrH = smem_u32(sAh), aAdrL = smem_u32(sAl);
    const uint32_t bAdrH = smem_u32(sBh), bAdrL = smem_u32(sBl);
    const uint32_t aoff = (uint32_t)(((warp_m * 64 + l15) * ASTRIDE + (lane >> 4) * 8) * 2);
    const uint32_t boff = (uint32_t)(((warp_n * 32 + (l15 & 7)) * ASTRIDE + ((l15 >> 3) * 8)) * 2);

    float acc[4][4][4];
#pragma unroll
    for (int mt = 0; mt < 4; mt++)
#pragma unroll
        for (int nt = 0; nt < 4; nt++)
#pragma unroll
            for (int j = 0; j < 4; j++) acc[mt][nt][j] = 0.f;

    // staging registers
    uint32_t hp[8], lp[8];
    uint4 bhr0, bhr1, blr0, blr1;

    auto load_chunk = [&](int k0) {
        const float4* af = (const float4*)(Arow[lrow] + k0 + lhalf);
#pragma unroll
        for (int c = 0; c < 4; c++) {
            float4 f = af[c];
            __nv_bfloat162 h0 = __floats2bfloat162_rn(f.x, f.y);
            __nv_bfloat162 h1 = __floats2bfloat162_rn(f.z, f.w);
            float lx = f.x - __bfloat162float(h0.x);
            float ly = f.y - __bfloat162float(h0.y);
            float lz = f.z - __bfloat162float(h1.x);
            float lw = f.w - __bfloat162float(h1.y);
            __nv_bfloat162 l0 = __floats2bfloat162_rn(lx, ly);
            __nv_bfloat162 l1 = __floats2bfloat162_rn(lz, lw);
            hp[2 * c]     = *(const uint32_t*)&h0;
            hp[2 * c + 1] = *(const uint32_t*)&h1;
            lp[2 * c]     = *(const uint32_t*)&l0;
            lp[2 * c + 1] = *(const uint32_t*)&l1;
        }
        bhr0 = *(const uint4*)(bHp + k0);
        bhr1 = *(const uint4*)(bHp + k0 + 8);
        blr0 = *(const uint4*)(bLp + k0);
        blr1 = *(const uint4*)(bLp + k0 + 8);
    };
    auto store_chunk = [&]() {
        *(uint4*)&sAh[lrow][lhalf]     = make_uint4(hp[0], hp[1], hp[2], hp[3]);
        *(uint4*)&sAh[lrow][lhalf + 8] = make_uint4(hp[4], hp[5], hp[6], hp[7]);
        *(uint4*)&sAl[lrow][lhalf]     = make_uint4(lp[0], lp[1], lp[2], lp[3]);
        *(uint4*)&sAl[lrow][lhalf + 8] = make_uint4(lp[4], lp[5], lp[6], lp[7]);
        *(uint4*)&sBh[lrow][lhalf]     = bhr0;
        *(uint4*)&sBh[lrow][lhalf + 8] = bhr1;
        *(uint4*)&sBl[lrow][lhalf]     = blr0;
        *(uint4*)&sBl[lrow][lhalf + 8] = blr1;
    };

    load_chunk(0);
    for (int i = 0; i < NCHUNK; i++) {
        __syncthreads();   // previous compute done; smem reusable
        store_chunk();
        __syncthreads();   // smem ready
        if (i + 1 < NCHUNK) load_chunk((i + 1) * BK);  // overlap next loads with mma

#pragma unroll
        for (int k16 = 0; k16 < 2; k16++) {
            uint32_t ah[4][4], al[4][4], bh[4][2], bl[4][2];
#pragma unroll
            for (int mt = 0; mt < 4; mt++) {
                uint32_t o = aoff + (uint32_t)((mt * 16 * ASTRIDE + k16 * 16) * 2);
                ldsm4(ah[mt], aAdrH + o);
                ldsm4(al[mt], aAdrL + o);
            }
#pragma unroll
            for (int nt = 0; nt < 4; nt++) {
                uint32_t o = boff + (uint32_t)((nt * 8 * ASTRIDE + k16 * 16) * 2);
                ldsm2(bh[nt], bAdrH + o);
                ldsm2(bl[nt], bAdrL + o);
            }
#pragma unroll
            for (int mt = 0; mt < 4; mt++)
#pragma unroll
                for (int nt = 0; nt < 4; nt++) {
                    mma16816(acc[mt][nt], ah[mt], bh[nt]);
                    mma16816(acc[mt][nt], ah[mt], bl[nt]);
                    mma16816(acc[mt][nt], al[mt], bh[nt]);
                }
        }
    }

    // ---- epilogue: bias add + store ----
    const int groupid = lane >> 2;
    const int t4      = lane & 3;
    float2 bv[4];
#pragma unroll
    for (int nt = 0; nt < 4; nt++)
        bv[nt] = *(const float2*)(bias + (size_t)e * DDIM + n0 + warp_n * 32 + nt * 8 + t4 * 2);

    float* OutB = GATHER ? g_h1 : g_h2;
#pragma unroll
    for (int mt = 0; mt < 4; mt++) {
        int r0 = m0 + warp_m * 64 + mt * 16 + groupid;
        int r1 = r0 + 8;
        float* p0 = OutB + ((size_t)e * TOK + r0) * DDIM + n0 + warp_n * 32 + t4 * 2;
        float* p1 = OutB + ((size_t)e * TOK + r1) * DDIM + n0 + warp_n * 32 + t4 * 2;
#pragma unroll
        for (int nt = 0; nt < 4; nt++) {
            if (r0 < cnt)
                *(float2*)(p0 + nt * 8) = make_float2(acc[mt][nt][0] + bv[nt].x,
                                                      acc[mt][nt][1] + bv[nt].y);
            if (r1 < cnt)
                *(float2*)(p1 + nt * 8) = make_float2(acc[mt][nt][2] + bv[nt].x,
                                                      acc[mt][nt][3] + bv[nt].y);
        }
    }
}

// ---------------------------------------------------------------------------
// 3/5) LayerNorm (warp per row, in place). WHICH=1: g_h1 + relu; WHICH=2: g_h2
// ---------------------------------------------------------------------------
template <int WHICH>
__global__ void ln_kernel(const float* __restrict__ w,
                          const float* __restrict__ b) {
    int gw = (blockIdx.x * blockDim.x + threadIdx.x) >> 5;
    int e   = gw >> 15;
    int pos = gw & (TOK - 1);
    if (pos >= g_cnt[e]) return;
    int lane = threadIdx.x & 31;
    float* row = (WHICH == 1 ? g_h1 : g_h2) + (size_t)gw * DDIM;

    float v[16];
    float s = 0.f;
#pragma unroll
    for (int i = 0; i < 16; i++) { v[i] = row[lane + i * 32]; s += v[i]; }
#pragma unroll
    for (int o = 16; o > 0; o >>= 1) s += __shfl_xor_sync(0xffffffffu, s, o);
    float mu = s * (1.f / DDIM);

    float q = 0.f;
#pragma unroll
    for (int i = 0; i < 16; i++) { float d = v[i] - mu; q += d * d; }
#pragma unroll
    for (int o = 16; o > 0; o >>= 1) q += __shfl_xor_sync(0xffffffffu, q, o);
    float rstd = rsqrtf(q * (1.f / DDIM) + LN_EPS);

    const float* we = w + e * DDIM;
    const float* be = b + e * DDIM;
#pragma unroll
    for (int i = 0; i < 16; i++) {
        int d = lane + i * 32;
        float y = (v[i] - mu) * rstd * we[d] + be[d];
        if (WHICH == 1) y = fmaxf(y, 0.f);
        row[d] = y;
    }
}

// ---------------------------------------------------------------------------
// 6) combine
// ---------------------------------------------------------------------------
__global__ void combine_kernel(const float* __restrict__ x,
                               float* __restrict__ out) {
    int gw   = (blockIdx.x * blockDim.x + threadIdx.x) >> 5;
    int lane = threadIdx.x & 31;
    const int t = gw;

    int   p0 = g_tokPair[t * 4 + 0], p1 = g_tokPair[t * 4 + 1];
    int   p2 = g_tokPair[t * 4 + 2], p3 = g_tokPair[t * 4 + 3];
    float w0 = g_tokW[t * 4 + 0], w1 = g_tokW[t * 4 + 1];
    float w2 = g_tokW[t * 4 + 2], w3 = g_tokW[t * 4 + 3];

    const float* ha = g_h2 + (size_t)p0 * DDIM;
    const float* hb = g_h2 + (size_t)p1 * DDIM;
    const float* hc = g_h2 + (size_t)p2 * DDIM;
    const float* hd = g_h2 + (size_t)p3 * DDIM;
    const float* xr = x + (size_t)t * DDIM;
    float* o_out = out + (size_t)t * DDIM;
    float* o_top = out + (size_t)BND + (size_t)t * DDIM;
    float* o_bot = out + 2 * (size_t)BND + (size_t)t * DDIM;

    float accd = 0.f;
#pragma unroll
    for (int i = 0; i < 16; i++) {
        int d = lane + i * 32;
        float top = w0 * ha[d] + w1 * hb[d];
        float bot = w2 * hc[d] + w3 * hd[d];
        o_top[d] = top;
        o_bot[d] = bot;
        o_out[d] = top + xr[d];
        float df = top - bot;
        accd += df * df;
    }
#pragma unroll
    for (int o = 16; o > 0; o >>= 1) accd += __shfl_xor_sync(0xffffffffu, accd, o);

    __shared__ float red[8];
    if (lane == 0) red[threadIdx.x >> 5] = accd;
    __syncthreads();
    if (threadIdx.x == 0) {
        float ssum = 0.f;
        for (int i = 0; i < 8; i++) ssum += red[i];
        g_part[blockIdx.x] = ssum;
    }
}

// ---------------------------------------------------------------------------
// 7) loss
// ---------------------------------------------------------------------------
__global__ void loss_kernel(float* __restrict__ out) {
    int w = threadIdx.x >> 5, lane = threadIdx.x & 31;
    __shared__ float lred[8];
    float s = 0.f;
    for (int i = lane; i < 512; i += 32) s += g_part[w * 512 + i];
#pragma unroll
    for (int o = 16; o > 0; o >>= 1) s += __shfl_xor_sync(0xffffffffu, s, o);
    if (lane == 0) lred[w] = 1.f / (sqrtf(s) + 1e-8f);
    __syncthreads();
    if (threadIdx.x == 0) {
        float a = 0.f;
        for (int i = 0; i < 8; i++) a += lred[i];
        out[(size_t)3 * BND] = a * (1.f / 8.f);
    }
}

// ---------------------------------------------------------------------------
// launch
// ---------------------------------------------------------------------------
extern "C" void kernel_launch(void* const* d_in, const int* in_sizes, int n_in,
                              void* d_out, int out_size) {
    const float* x    = (const float*)d_in[0];
    const float* Wg   = (const float*)d_in[1];
    const float* bg   = (const float*)d_in[2];
    const float* W1   = (const float*)d_in[3];
    const float* b1   = (const float*)d_in[4];
    const float* ln1w = (const float*)d_in[5];
    const float* ln1b = (const float*)d_in[6];
    const float* W2   = (const float*)d_in[7];
    const float* b2   = (const float*)d_in[8];
    const float* ln2w = (const float*)d_in[9];
    const float* ln2b = (const float*)d_in[10];
    float* out = (float*)d_out;

    init_kernel<<<1, 32>>>();
    gating_kernel<<<TOK * 32 / 256, 256>>>(x, Wg, bg);

    dim3 wgrid(DDIM / 32, DDIM / 32, NEXP);
    wconv_kernel<1><<<wgrid, dim3(32, 8)>>>(W1);
    wconv_kernel<2><<<wgrid, dim3(32, 8)>>>(W2);

    dim3 ggrid(DDIM / BN, TOK / BM, NEXP);   // (4, 256, 8)
    gemm_mma<true><<<ggrid, 256>>>(x, b1);
    ln_kernel<1><<<NEXP * TOK * 32 / 256, 256>>>(ln1w, ln1b);
    gemm_mma<false><<<ggrid, 256>>>(nullptr, b2);
    ln_kernel<2><<<NEXP * TOK * 32 / 256, 256>>>(ln2w, ln2b);

    combine_kernel<<<TOK * 32 / 256, 256>>>(x, out);
    loss_kernel<<<1, 256>>>(out);
}

// round 4
// speedup vs baseline: 2.0057x; 1.4235x over previous
#include <cuda_runtime.h>
#include <cuda_bf16.h>
#include <math.h>
#include <stdint.h>

// Problem constants
#define TOK   32768          // B*N = 8*4096
#define NEXP  8
#define DDIM  512
#define BND   16777216       // TOK * DDIM
#define LN_EPS 1e-5f

// GEMM tile config
#define BM 128
#define BN 256
#define BK 32
#define NCHUNK (DDIM / BK)   // 16
// smem stage layout (bytes): rows padded to 40 bf16 = 80B (conflict-free ldsm)
#define AH_OFF 0
#define AL_OFF 10240
#define BH_OFF 20480
#define BL_OFF 40960
#define STAGE_B 61440
#define NSTAGE 3
#define SMEM_DYN (NSTAGE * STAGE_B)   // 184320

// ---------------------------------------------------------------------------
// Scratch (__device__ globals; no allocations allowed)
// ---------------------------------------------------------------------------
__device__ int   g_cnt[NEXP];
__device__ int   g_pairTok[NEXP * TOK];
__device__ int   g_tokPair[TOK * 4];
__device__ float g_tokW[TOK * 4];
__device__ float g_h1[(size_t)NEXP * TOK * DDIM];
__device__ float g_h2[(size_t)NEXP * TOK * DDIM];
__device__ float g_part[4096];
__device__ __nv_bfloat16 g_ah[(size_t)NEXP * TOK * DDIM];   // A hi (gemm input rows)
__device__ __nv_bfloat16 g_al[(size_t)NEXP * TOK * DDIM];   // A lo
__device__ __nv_bfloat16 g_w1t_hi[(size_t)NEXP * DDIM * DDIM];
__device__ __nv_bfloat16 g_w1t_lo[(size_t)NEXP * DDIM * DDIM];
__device__ __nv_bfloat16 g_w2t_hi[(size_t)NEXP * DDIM * DDIM];
__device__ __nv_bfloat16 g_w2t_lo[(size_t)NEXP * DDIM * DDIM];

// ---------------------------------------------------------------------------
// Helpers
// ---------------------------------------------------------------------------
__device__ __forceinline__ uint32_t smem_u32(const void* p) {
    uint32_t a;
    asm("{ .reg .u64 t; cvta.to.shared.u64 t, %1; cvt.u32.u64 %0, t; }" : "=r"(a) : "l"(p));
    return a;
}
__device__ __forceinline__ void cp16(uint32_t dst, const void* src) {
    asm volatile("cp.async.cg.shared.global [%0], [%1], 16;" :: "r"(dst), "l"(src));
}
#define CP_COMMIT() asm volatile("cp.async.commit_group;" ::: "memory")
#define CP_WAIT1()  asm volatile("cp.async.wait_group 1;" ::: "memory")
__device__ __forceinline__ void ldsm4(uint32_t* r, uint32_t addr) {
    asm volatile("ldmatrix.sync.aligned.m8n8.x4.shared.b16 {%0,%1,%2,%3}, [%4];"
                 : "=r"(r[0]), "=r"(r[1]), "=r"(r[2]), "=r"(r[3]) : "r"(addr));
}
__device__ __forceinline__ void mma16816(float* c, const uint32_t* a, const uint32_t* b) {
    asm volatile(
        "mma.sync.aligned.m16n8k16.row.col.f32.bf16.bf16.f32 "
        "{%0,%1,%2,%3}, {%4,%5,%6,%7}, {%8,%9}, {%0,%1,%2,%3};"
        : "+f"(c[0]), "+f"(c[1]), "+f"(c[2]), "+f"(c[3])
        : "r"(a[0]), "r"(a[1]), "r"(a[2]), "r"(a[3]), "r"(b[0]), "r"(b[1]));
}

// ---------------------------------------------------------------------------
// 0) zero counters
// ---------------------------------------------------------------------------
__global__ void init_kernel() {
    if (threadIdx.x < NEXP) g_cnt[threadIdx.x] = 0;
}

// ---------------------------------------------------------------------------
// 1) gating
// ---------------------------------------------------------------------------
__global__ void gating_kernel(const float* __restrict__ x,
                              const float* __restrict__ Wg,
                              const float* __restrict__ bg) {
    int gw = (blockIdx.x * blockDim.x + threadIdx.x) >> 5;
    if (gw >= TOK) return;
    int lane = threadIdx.x & 31;
    const float* xr = x + (size_t)gw * DDIM;

    float s[NEXP];
#pragma unroll
    for (int e = 0; e < NEXP; e++) s[e] = 0.f;
    for (int d = lane; d < DDIM; d += 32) {
        float xv = xr[d];
        const float* wr = Wg + d * NEXP;
#pragma unroll
        for (int e = 0; e < NEXP; e++) s[e] += xv * wr[e];
    }
#pragma unroll
    for (int e = 0; e < NEXP; e++) {
#pragma unroll
        for (int o = 16; o > 0; o >>= 1)
            s[e] += __shfl_xor_sync(0xffffffffu, s[e], o);
    }
    if (lane == 0) {
#pragma unroll
        for (int e = 0; e < NEXP; e++) s[e] += bg[e];
        int i0 = 0; float v0 = s[0];
        for (int e = 1; e < NEXP; e++) if (s[e] > v0) { v0 = s[e]; i0 = e; }
        int i1 = -1; float v1 = -1e30f;
        for (int e = 0; e < NEXP; e++) if (e != i0 && s[e] > v1) { v1 = s[e]; i1 = e; }
        int j0 = 0; float u0 = s[0];
        for (int e = 1; e < NEXP; e++) if (s[e] < u0) { u0 = s[e]; j0 = e; }
        int j1 = -1; float u1 = 1e30f;
        for (int e = 0; e < NEXP; e++) if (e != j0 && s[e] < u1) { u1 = s[e]; j1 = e; }

        float et  = expf(v1 - v0);
        float wt0 = 1.f / (1.f + et);
        float wt1 = et * wt0;
        float eb  = expf(u0 - u1);
        float wb1 = 1.f / (1.f + eb);
        float wb0 = eb * wb1;

        int p;
        p = atomicAdd(&g_cnt[i0], 1);
        g_pairTok[i0 * TOK + p] = gw;
        g_tokPair[gw * 4 + 0] = i0 * TOK + p;  g_tokW[gw * 4 + 0] = wt0;
        p = atomicAdd(&g_cnt[i1], 1);
        g_pairTok[i1 * TOK + p] = gw;
        g_tokPair[gw * 4 + 1] = i1 * TOK + p;  g_tokW[gw * 4 + 1] = wt1;
        p = atomicAdd(&g_cnt[j0], 1);
        g_pairTok[j0 * TOK + p] = gw;
        g_tokPair[gw * 4 + 2] = j0 * TOK + p;  g_tokW[gw * 4 + 2] = wb0;
        p = atomicAdd(&g_cnt[j1], 1);
        g_pairTok[j1 * TOK + p] = gw;
        g_tokPair[gw * 4 + 3] = j1 * TOK + p;  g_tokW[gw * 4 + 3] = wb1;
    }
}

// ---------------------------------------------------------------------------
// 1b) weight prep: W[e][k][n] fp32 -> Wt_hi/lo[e][n][k] bf16 (transpose + split)
// ---------------------------------------------------------------------------
template <int WHICH>
__global__ void wconv_kernel(const float* __restrict__ W) {
    __shared__ float t[32][33];
    int e  = blockIdx.z;
    int kb = blockIdx.x * 32, nb = blockIdx.y * 32;
    const float* src = W + (size_t)e * DDIM * DDIM;
    int tx = threadIdx.x, ty = threadIdx.y;
#pragma unroll
    for (int r = ty; r < 32; r += 8)
        t[r][tx] = src[(size_t)(kb + r) * DDIM + nb + tx];
    __syncthreads();
    __nv_bfloat16* Th = (WHICH == 1) ? g_w1t_hi : g_w2t_hi;
    __nv_bfloat16* Tl = (WHICH == 1) ? g_w1t_lo : g_w2t_lo;
#pragma unroll
    for (int r = ty; r < 32; r += 8) {
        float v = t[tx][r];  // = W[kb+tx][nb+r]
        __nv_bfloat16 h = __float2bfloat16(v);
        __nv_bfloat16 l = __float2bfloat16(v - __bfloat162float(h));
        size_t o = ((size_t)e * DDIM + (nb + r)) * DDIM + kb + tx;
        Th[o] = h;
        Tl[o] = l;
    }
}

// ---------------------------------------------------------------------------
// 1c) A prep: gather x rows by routed pair, split fp32 -> bf16 hi/lo
//     one warp per (token, slot)
// ---------------------------------------------------------------------------
__global__ void aprep_kernel(const float* __restrict__ x) {
    int gw = (blockIdx.x * blockDim.x + threadIdx.x) >> 5;   // 0..TOK*4
    int t = gw >> 2, j = gw & 3;
    int lane = threadIdx.x & 31;
    int pair = g_tokPair[t * 4 + j];
    const float4* xr = (const float4*)(x + (size_t)t * DDIM);
    __nv_bfloat16* oh = g_ah + (size_t)pair * DDIM;
    __nv_bfloat16* ol = g_al + (size_t)pair * DDIM;
#pragma unroll
    for (int i = 0; i < 4; i++) {
        int c = lane + i * 32;          // float4 index
        float4 f = xr[c];
        __nv_bfloat162 h0 = __floats2bfloat162_rn(f.x, f.y);
        __nv_bfloat162 h1 = __floats2bfloat162_rn(f.z, f.w);
        __nv_bfloat162 l0 = __floats2bfloat162_rn(f.x - __bfloat162float(h0.x),
                                                  f.y - __bfloat162float(h0.y));
        __nv_bfloat162 l1 = __floats2bfloat162_rn(f.z - __bfloat162float(h1.x),
                                                  f.w - __bfloat162float(h1.y));
        *(uint2*)(oh + c * 4) = make_uint2(*(uint32_t*)&h0, *(uint32_t*)&h1);
        *(uint2*)(ol + c * 4) = make_uint2(*(uint32_t*)&l0, *(uint32_t*)&l1);
    }
}

// ---------------------------------------------------------------------------
// 2/4) bf16x3 HMMA GEMM, cp.async 3-stage pipeline.
//      BM=128, BN=256, BK=32; 256 threads = 8 warps (2 x 4), warp tile 64x64.
//      A rows from g_ah/g_al (pair-slot space); out fp32 (g_h1 or g_h2).
// ---------------------------------------------------------------------------
template <int WHICH>
__global__ void __launch_bounds__(256, 1) gemm_mma(const float* __restrict__ bias) {
    const int e   = blockIdx.z;
    const int cnt = g_cnt[e];
    const int m0  = blockIdx.y * BM;
    if (m0 >= cnt) return;
    const int n0  = blockIdx.x * BN;

    extern __shared__ char dsm[];
    const uint32_t sbase = smem_u32(dsm);

    const int tid  = threadIdx.x;
    const int wid  = tid >> 5;
    const int lane = tid & 31;

    const __nv_bfloat16* wtH = (WHICH == 1) ? g_w1t_hi : g_w2t_hi;
    const __nv_bfloat16* wtL = (WHICH == 1) ? g_w1t_lo : g_w2t_lo;

    // ---- loader precompute: 12 x 16B segments per thread per stage ----
    const __nv_bfloat16* src[12];
    uint32_t dst[12];
#pragma unroll
    for (int j = 0; j < 12; j++) {
        int gid = tid + j * 256;
        if (gid < 1024) {                       // A (hi then lo)
            int mat = gid >> 9;
            int idx = gid & 511;
            int row = idx >> 2, ks = idx & 3;
            int rr = m0 + row; if (rr > cnt - 1) rr = cnt - 1;
            src[j] = (mat ? g_al : g_ah) + ((size_t)e * TOK + rr) * DDIM + ks * 8;
            dst[j] = (mat ? AL_OFF : AH_OFF) + row * 80 + ks * 16;
        } else {                                // B (hi then lo)
            int g2  = gid - 1024;
            int mat = g2 >> 10;
            int idx = g2 & 1023;
            int row = idx >> 2, ks = idx & 3;
            src[j] = (mat ? wtL : wtH) + ((size_t)e * DDIM + n0 + row) * DDIM + ks * 8;
            dst[j] = (mat ? BL_OFF : BH_OFF) + row * 80 + ks * 16;
        }
    }

    auto issue = [&](int chunk, int s) {
        const int k0 = chunk * BK;
        const uint32_t sb = sbase + s * STAGE_B;
#pragma unroll
        for (int j = 0; j < 12; j++) cp16(sb + dst[j], src[j] + k0);
    };

    // warp layout: warp_m = wid>>2 (64 rows), warp_n = wid&3 (64 cols)
    const int warp_m = wid >> 2;
    const int warp_n = wid & 3;
    const int l15 = lane & 15;
    // A frag byte offsets within stage
    const uint32_t aoff = (uint32_t)((warp_m * 64 + l15) * 80 + (lane >> 4) * 16);
    // B frag: rows warp_n*64 + p*16 + (lane>>4)*8 + (lane&7), col half (lane>>3)&1
    const uint32_t boff = (uint32_t)((warp_n * 64 + (lane >> 4) * 8 + (lane & 7)) * 80 +
                                     ((lane >> 3) & 1) * 16);

    float acc[4][8][4];
#pragma unroll
    for (int mt = 0; mt < 4; mt++)
#pragma unroll
        for (int nt = 0; nt < 8; nt++)
#pragma unroll
            for (int q = 0; q < 4; q++) acc[mt][nt][q] = 0.f;

    issue(0, 0); CP_COMMIT();
    issue(1, 1); CP_COMMIT();

    for (int i = 0; i < NCHUNK; i++) {
        const int s = i % NSTAGE;
        CP_WAIT1();
        __syncthreads();
        if (i + 2 < NCHUNK) issue(i + 2, (i + 2) % NSTAGE);
        CP_COMMIT();

        const uint32_t sb = sbase + s * STAGE_B;
        const uint32_t aH = sb + AH_OFF + aoff;
        const uint32_t aL = sb + AL_OFF + aoff;
        const uint32_t bH = sb + BH_OFF + boff;
        const uint32_t bL = sb + BL_OFF + boff;
#pragma unroll
        for (int k16 = 0; k16 < 2; k16++) {
            uint32_t bh[8][2], bl[8][2];
#pragma unroll
            for (int p = 0; p < 4; p++) {
                uint32_t r4[4];
                ldsm4(r4, bH + p * 16 * 80 + k16 * 32);
                bh[2 * p][0] = r4[0]; bh[2 * p][1] = r4[1];
                bh[2 * p + 1][0] = r4[2]; bh[2 * p + 1][1] = r4[3];
                ldsm4(r4, bL + p * 16 * 80 + k16 * 32);
                bl[2 * p][0] = r4[0]; bl[2 * p][1] = r4[1];
                bl[2 * p + 1][0] = r4[2]; bl[2 * p + 1][1] = r4[3];
            }
#pragma unroll
            for (int mt = 0; mt < 4; mt++) {
                uint32_t ah[4], al[4];
                ldsm4(ah, aH + mt * 16 * 80 + k16 * 32);
                ldsm4(al, aL + mt * 16 * 80 + k16 * 32);
#pragma unroll
                for (int nt = 0; nt < 8; nt++) {
                    mma16816(acc[mt][nt], ah, bh[nt]);
                    mma16816(acc[mt][nt], ah, bl[nt]);
                    mma16816(acc[mt][nt], al, bh[nt]);
                }
            }
        }
    }

    // ---- epilogue: bias add + fp32 store ----
    const int groupid = lane >> 2;
    const int t4      = lane & 3;
    float2 bv[8];
#pragma unroll
    for (int nt = 0; nt < 8; nt++)
        bv[nt] = *(const float2*)(bias + (size_t)e * DDIM + n0 + warp_n * 64 + nt * 8 + t4 * 2);

    float* OutB = (WHICH == 1) ? g_h1 : g_h2;
#pragma unroll
    for (int mt = 0; mt < 4; mt++) {
        int r0 = m0 + warp_m * 64 + mt * 16 + groupid;
        int r1 = r0 + 8;
        float* p0 = OutB + ((size_t)e * TOK + r0) * DDIM + n0 + warp_n * 64 + t4 * 2;
        float* p1 = OutB + ((size_t)e * TOK + r1) * DDIM + n0 + warp_n * 64 + t4 * 2;
#pragma unroll
        for (int nt = 0; nt < 8; nt++) {
            if (r0 < cnt)
                *(float2*)(p0 + nt * 8) = make_float2(acc[mt][nt][0] + bv[nt].x,
                                                      acc[mt][nt][1] + bv[nt].y);
            if (r1 < cnt)
                *(float2*)(p1 + nt * 8) = make_float2(acc[mt][nt][2] + bv[nt].x,
                                                      acc[mt][nt][3] + bv[nt].y);
        }
    }
}

// ---------------------------------------------------------------------------
// 3) LN1 + relu: reads g_h1 fp32, writes bf16 hi/lo into g_ah/g_al
// ---------------------------------------------------------------------------
__global__ void ln1_kernel(const float* __restrict__ w,
                           const float* __restrict__ b) {
    int gw = (blockIdx.x * blockDim.x + threadIdx.x) >> 5;
    int e   = gw >> 15;
    int pos = gw & (TOK - 1);
    if (pos >= g_cnt[e]) return;
    int lane = threadIdx.x & 31;
    const float* row = g_h1 + (size_t)gw * DDIM;

    float v[16];
    float s = 0.f;
#pragma unroll
    for (int i = 0; i < 16; i++) { v[i] = row[lane + i * 32]; s += v[i]; }
#pragma unroll
    for (int o = 16; o > 0; o >>= 1) s += __shfl_xor_sync(0xffffffffu, s, o);
    float mu = s * (1.f / DDIM);

    float q = 0.f;
#pragma unroll
    for (int i = 0; i < 16; i++) { float d = v[i] - mu; q += d * d; }
#pragma unroll
    for (int o = 16; o > 0; o >>= 1) q += __shfl_xor_sync(0xffffffffu, q, o);
    float rstd = rsqrtf(q * (1.f / DDIM) + LN_EPS);

    const float* we = w + e * DDIM;
    const float* be = b + e * DDIM;
    __nv_bfloat16* oh = g_ah + (size_t)gw * DDIM;
    __nv_bfloat16* ol = g_al + (size_t)gw * DDIM;
#pragma unroll
    for (int i = 0; i < 16; i++) {
        int d = lane + i * 32;
        float y = fmaxf((v[i] - mu) * rstd * we[d] + be[d], 0.f);
        __nv_bfloat16 h = __float2bfloat16(y);
        oh[d] = h;
        ol[d] = __float2bfloat16(y - __bfloat162float(h));
    }
}

// ---------------------------------------------------------------------------
// 5) LN2: in-place fp32 on g_h2
// ---------------------------------------------------------------------------
__global__ void ln2_kernel(const float* __restrict__ w,
                           const float* __restrict__ b) {
    int gw = (blockIdx.x * blockDim.x + threadIdx.x) >> 5;
    int e   = gw >> 15;
    int pos = gw & (TOK - 1);
    if (pos >= g_cnt[e]) return;
    int lane = threadIdx.x & 31;
    float* row = g_h2 + (size_t)gw * DDIM;

    float v[16];
    float s = 0.f;
#pragma unroll
    for (int i = 0; i < 16; i++) { v[i] = row[lane + i * 32]; s += v[i]; }
#pragma unroll
    for (int o = 16; o > 0; o >>= 1) s += __shfl_xor_sync(0xffffffffu, s, o);
    float mu = s * (1.f / DDIM);

    float q = 0.f;
#pragma unroll
    for (int i = 0; i < 16; i++) { float d = v[i] - mu; q += d * d; }
#pragma unroll
    for (int o = 16; o > 0; o >>= 1) q += __shfl_xor_sync(0xffffffffu, q, o);
    float rstd = rsqrtf(q * (1.f / DDIM) + LN_EPS);

    const float* we = w + e * DDIM;
    const float* be = b + e * DDIM;
#pragma unroll
    for (int i = 0; i < 16; i++) {
        int d = lane + i * 32;
        row[d] = (v[i] - mu) * rstd * we[d] + be[d];
    }
}

// ---------------------------------------------------------------------------
// 6) combine
// ---------------------------------------------------------------------------
__global__ void combine_kernel(const float* __restrict__ x,
                               float* __restrict__ out) {
    int gw   = (blockIdx.x * blockDim.x + threadIdx.x) >> 5;
    int lane = threadIdx.x & 31;
    const int t = gw;

    int   p0 = g_tokPair[t * 4 + 0], p1 = g_tokPair[t * 4 + 1];
    int   p2 = g_tokPair[t * 4 + 2], p3 = g_tokPair[t * 4 + 3];
    float w0 = g_tokW[t * 4 + 0], w1 = g_tokW[t * 4 + 1];
    float w2 = g_tokW[t * 4 + 2], w3 = g_tokW[t * 4 + 3];

    const float* ha = g_h2 + (size_t)p0 * DDIM;
    const float* hb = g_h2 + (size_t)p1 * DDIM;
    const float* hc = g_h2 + (size_t)p2 * DDIM;
    const float* hd = g_h2 + (size_t)p3 * DDIM;
    const float* xr = x + (size_t)t * DDIM;
    float* o_out = out + (size_t)t * DDIM;
    float* o_top = out + (size_t)BND + (size_t)t * DDIM;
    float* o_bot = out + 2 * (size_t)BND + (size_t)t * DDIM;

    float accd = 0.f;
#pragma unroll
    for (int i = 0; i < 16; i++) {
        int d = lane + i * 32;
        float top = w0 * ha[d] + w1 * hb[d];
        float bot = w2 * hc[d] + w3 * hd[d];
        o_top[d] = top;
        o_bot[d] = bot;
        o_out[d] = top + xr[d];
        float df = top - bot;
        accd += df * df;
    }
#pragma unroll
    for (int o = 16; o > 0; o >>= 1) accd += __shfl_xor_sync(0xffffffffu, accd, o);

    __shared__ float red[8];
    if (lane == 0) red[threadIdx.x >> 5] = accd;
    __syncthreads();
    if (threadIdx.x == 0) {
        float ssum = 0.f;
        for (int i = 0; i < 8; i++) ssum += red[i];
        g_part[blockIdx.x] = ssum;
    }
}

// ---------------------------------------------------------------------------
// 7) loss
// ---------------------------------------------------------------------------
__global__ void loss_kernel(float* __restrict__ out) {
    int w = threadIdx.x >> 5, lane = threadIdx.x & 31;
    __shared__ float lred[8];
    float s = 0.f;
    for (int i = lane; i < 512; i += 32) s += g_part[w * 512 + i];
#pragma unroll
    for (int o = 16; o > 0; o >>= 1) s += __shfl_xor_sync(0xffffffffu, s, o);
    if (lane == 0) lred[w] = 1.f / (sqrtf(s) + 1e-8f);
    __syncthreads();
    if (threadIdx.x == 0) {
        float a = 0.f;
        for (int i = 0; i < 8; i++) a += lred[i];
        out[(size_t)3 * BND] = a * (1.f / 8.f);
    }
}

// ---------------------------------------------------------------------------
// launch
// ---------------------------------------------------------------------------
extern "C" void kernel_launch(void* const* d_in, const int* in_sizes, int n_in,
                              void* d_out, int out_size) {
    const float* x    = (const float*)d_in[0];
    const float* Wg   = (const float*)d_in[1];
    const float* bg   = (const float*)d_in[2];
    const float* W1   = (const float*)d_in[3];
    const float* b1   = (const float*)d_in[4];
    const float* ln1w = (const float*)d_in[5];
    const float* ln1b = (const float*)d_in[6];
    const float* W2   = (const float*)d_in[7];
    const float* b2   = (const float*)d_in[8];
    const float* ln2w = (const float*)d_in[9];
    const float* ln2b = (const float*)d_in[10];
    float* out = (float*)d_out;

    static int smem_set = 0;
    if (!smem_set) {
        cudaFuncSetAttribute(gemm_mma<1>, cudaFuncAttributeMaxDynamicSharedMemorySize, SMEM_DYN);
        cudaFuncSetAttribute(gemm_mma<2>, cudaFuncAttributeMaxDynamicSharedMemorySize, SMEM_DYN);
        smem_set = 1;
    }

    init_kernel<<<1, 32>>>();
    gating_kernel<<<TOK * 32 / 256, 256>>>(x, Wg, bg);

    dim3 wgrid(DDIM / 32, DDIM / 32, NEXP);
    wconv_kernel<1><<<wgrid, dim3(32, 8)>>>(W1);
    wconv_kernel<2><<<wgrid, dim3(32, 8)>>>(W2);
    aprep_kernel<<<TOK * 4 * 32 / 256, 256>>>(x);

    dim3 ggrid(DDIM / BN, TOK / BM, NEXP);   // (2, 256, 8)
    gemm_mma<1><<<ggrid, 256, SMEM_DYN>>>(b1);
    ln1_kernel<<<NEXP * TOK * 32 / 256, 256>>>(ln1w, ln1b);
    gemm_mma<2><<<ggrid, 256, SMEM_DYN>>>(b2);
    ln2_kernel<<<NEXP * TOK * 32 / 256, 256>>>(ln2w, ln2b);

    combine_kernel<<<TOK * 32 / 256, 256>>>(x, out);
    loss_kernel<<<1, 256>>>(out);
}

// round 5
// speedup vs baseline: 2.1744x; 1.0841x over previous
#include <cuda_runtime.h>
#include <cuda_bf16.h>
#include <math.h>
#include <stdint.h>

// Problem constants
#define TOK   32768          // B*N = 8*4096
#define NEXP  8
#define DDIM  512
#define BND   16777216       // TOK * DDIM
#define LN_EPS 1e-5f

// GEMM tile config
#define BM 128
#define BN 256
#define BK 32
#define NCHUNK (DDIM / BK)   // 16
// smem stage layout (bytes): rows padded to 40 bf16 = 80B (conflict-free ldsm)
#define AH_OFF 0
#define AL_OFF 10240
#define BH_OFF 20480
#define BL_OFF 40960
#define STAGE_B 61440
#define NSTAGE 3
#define SMEM_DYN (NSTAGE * STAGE_B)   // 184320

// ---------------------------------------------------------------------------
// Scratch (__device__ globals; no allocations allowed)
// ---------------------------------------------------------------------------
__device__ int   g_cnt[NEXP];
__device__ int   g_pairTok[NEXP * TOK];
__device__ int   g_tokPair[TOK * 4];
__device__ float g_tokW[TOK * 4];
__device__ float g_h1[(size_t)NEXP * TOK * DDIM];
__device__ float g_h2[(size_t)NEXP * TOK * DDIM];
__device__ float g_part[4096];
__device__ __nv_bfloat16 g_xh[(size_t)TOK * DDIM];          // x split hi (token space)
__device__ __nv_bfloat16 g_xl[(size_t)TOK * DDIM];          // x split lo
__device__ __nv_bfloat16 g_ah[(size_t)NEXP * TOK * DDIM];   // ln1 out hi (pair space)
__device__ __nv_bfloat16 g_al[(size_t)NEXP * TOK * DDIM];   // ln1 out lo
__device__ __nv_bfloat16 g_w1t_hi[(size_t)NEXP * DDIM * DDIM];
__device__ __nv_bfloat16 g_w1t_lo[(size_t)NEXP * DDIM * DDIM];
__device__ __nv_bfloat16 g_w2t_hi[(size_t)NEXP * DDIM * DDIM];
__device__ __nv_bfloat16 g_w2t_lo[(size_t)NEXP * DDIM * DDIM];

// ---------------------------------------------------------------------------
// Helpers
// ---------------------------------------------------------------------------
__device__ __forceinline__ uint32_t smem_u32(const void* p) {
    uint32_t a;
    asm("{ .reg .u64 t; cvta.to.shared.u64 t, %1; cvt.u32.u64 %0, t; }" : "=r"(a) : "l"(p));
    return a;
}
__device__ __forceinline__ void cp16(uint32_t dst, const void* src) {
    asm volatile("cp.async.cg.shared.global [%0], [%1], 16;" :: "r"(dst), "l"(src));
}
#define CP_COMMIT() asm volatile("cp.async.commit_group;" ::: "memory")
#define CP_WAIT1()  asm volatile("cp.async.wait_group 1;" ::: "memory")
__device__ __forceinline__ void ldsm4(uint32_t* r, uint32_t addr) {
    asm volatile("ldmatrix.sync.aligned.m8n8.x4.shared.b16 {%0,%1,%2,%3}, [%4];"
                 : "=r"(r[0]), "=r"(r[1]), "=r"(r[2]), "=r"(r[3]) : "r"(addr));
}
__device__ __forceinline__ void mma16816(float* c, const uint32_t* a, const uint32_t* b) {
    asm volatile(
        "mma.sync.aligned.m16n8k16.row.col.f32.bf16.bf16.f32 "
        "{%0,%1,%2,%3}, {%4,%5,%6,%7}, {%8,%9}, {%0,%1,%2,%3};"
        : "+f"(c[0]), "+f"(c[1]), "+f"(c[2]), "+f"(c[3])
        : "r"(a[0]), "r"(a[1]), "r"(a[2]), "r"(a[3]), "r"(b[0]), "r"(b[1]));
}

// ---------------------------------------------------------------------------
// 0) zero counters
// ---------------------------------------------------------------------------
__global__ void init_kernel() {
    if (threadIdx.x < NEXP) g_cnt[threadIdx.x] = 0;
}

// ---------------------------------------------------------------------------
// 1) gating: scores + routing + x bf16 hi/lo split (token space)
// ---------------------------------------------------------------------------
__global__ void gating_kernel(const float* __restrict__ x,
                              const float* __restrict__ Wg,
                              const float* __restrict__ bg) {
    int gw = (blockIdx.x * blockDim.x + threadIdx.x) >> 5;
    if (gw >= TOK) return;
    int lane = threadIdx.x & 31;
    const float* xr = x + (size_t)gw * DDIM;
    __nv_bfloat16* xh = g_xh + (size_t)gw * DDIM;
    __nv_bfloat16* xl = g_xl + (size_t)gw * DDIM;

    float s[NEXP];
#pragma unroll
    for (int e = 0; e < NEXP; e++) s[e] = 0.f;
#pragma unroll
    for (int i = 0; i < 16; i++) {
        int d = lane + i * 32;
        float xv = xr[d];
        const float* wr = Wg + d * NEXP;
#pragma unroll
        for (int e = 0; e < NEXP; e++) s[e] += xv * wr[e];
        __nv_bfloat16 h = __float2bfloat16(xv);
        xh[d] = h;
        xl[d] = __float2bfloat16(xv - __bfloat162float(h));
    }
#pragma unroll
    for (int e = 0; e < NEXP; e++) {
#pragma unroll
        for (int o = 16; o > 0; o >>= 1)
            s[e] += __shfl_xor_sync(0xffffffffu, s[e], o);
    }
    if (lane == 0) {
#pragma unroll
        for (int e = 0; e < NEXP; e++) s[e] += bg[e];
        int i0 = 0; float v0 = s[0];
        for (int e = 1; e < NEXP; e++) if (s[e] > v0) { v0 = s[e]; i0 = e; }
        int i1 = -1; float v1 = -1e30f;
        for (int e = 0; e < NEXP; e++) if (e != i0 && s[e] > v1) { v1 = s[e]; i1 = e; }
        int j0 = 0; float u0 = s[0];
        for (int e = 1; e < NEXP; e++) if (s[e] < u0) { u0 = s[e]; j0 = e; }
        int j1 = -1; float u1 = 1e30f;
        for (int e = 0; e < NEXP; e++) if (e != j0 && s[e] < u1) { u1 = s[e]; j1 = e; }

        float et  = expf(v1 - v0);
        float wt0 = 1.f / (1.f + et);
        float wt1 = et * wt0;
        float eb  = expf(u0 - u1);
        float wb1 = 1.f / (1.f + eb);
        float wb0 = eb * wb1;

        int p;
        p = atomicAdd(&g_cnt[i0], 1);
        g_pairTok[i0 * TOK + p] = gw;
        g_tokPair[gw * 4 + 0] = i0 * TOK + p;  g_tokW[gw * 4 + 0] = wt0;
        p = atomicAdd(&g_cnt[i1], 1);
        g_pairTok[i1 * TOK + p] = gw;
        g_tokPair[gw * 4 + 1] = i1 * TOK + p;  g_tokW[gw * 4 + 1] = wt1;
        p = atomicAdd(&g_cnt[j0], 1);
        g_pairTok[j0 * TOK + p] = gw;
        g_tokPair[gw * 4 + 2] = j0 * TOK + p;  g_tokW[gw * 4 + 2] = wb0;
        p = atomicAdd(&g_cnt[j1], 1);
        g_pairTok[j1 * TOK + p] = gw;
        g_tokPair[gw * 4 + 3] = j1 * TOK + p;  g_tokW[gw * 4 + 3] = wb1;
    }
}

// ---------------------------------------------------------------------------
// 1b) weight prep: W[e][k][n] fp32 -> Wt_hi/lo[e][n][k] bf16 (transpose + split)
// ---------------------------------------------------------------------------
template <int WHICH>
__global__ void wconv_kernel(const float* __restrict__ W) {
    __shared__ float t[32][33];
    int e  = blockIdx.z;
    int kb = blockIdx.x * 32, nb = blockIdx.y * 32;
    const float* src = W + (size_t)e * DDIM * DDIM;
    int tx = threadIdx.x, ty = threadIdx.y;
#pragma unroll
    for (int r = ty; r < 32; r += 8)
        t[r][tx] = src[(size_t)(kb + r) * DDIM + nb + tx];
    __syncthreads();
    __nv_bfloat16* Th = (WHICH == 1) ? g_w1t_hi : g_w2t_hi;
    __nv_bfloat16* Tl = (WHICH == 1) ? g_w1t_lo : g_w2t_lo;
#pragma unroll
    for (int r = ty; r < 32; r += 8) {
        float v = t[tx][r];  // = W[kb+tx][nb+r]
        __nv_bfloat16 h = __float2bfloat16(v);
        __nv_bfloat16 l = __float2bfloat16(v - __bfloat162float(h));
        size_t o = ((size_t)e * DDIM + (nb + r)) * DDIM + kb + tx;
        Th[o] = h;
        Tl[o] = l;
    }
}

// ---------------------------------------------------------------------------
// 2/4) bf16x3 HMMA GEMM, cp.async 3-stage pipeline.
//      BM=128, BN=256, BK=32; 256 threads = 8 warps (2 x 4), warp tile 64x64.
//      WHICH=1: A = g_xh/g_xl gathered via pairTok; out g_h1.
//      WHICH=2: A = g_ah/g_al pair-space (ln1 out); out g_h2.
// ---------------------------------------------------------------------------
template <int WHICH>
__global__ void __launch_bounds__(256, 1) gemm_mma(const float* __restrict__ bias) {
    const int e   = blockIdx.z;
    const int cnt = g_cnt[e];
    const int m0  = blockIdx.y * BM;
    if (m0 >= cnt) return;
    const int n0  = blockIdx.x * BN;

    extern __shared__ char dsm[];
    const uint32_t sbase = smem_u32(dsm);

    const int tid  = threadIdx.x;
    const int wid  = tid >> 5;
    const int lane = tid & 31;

    const __nv_bfloat16* wtH = (WHICH == 1) ? g_w1t_hi : g_w2t_hi;
    const __nv_bfloat16* wtL = (WHICH == 1) ? g_w1t_lo : g_w2t_lo;

    // ---- loader precompute: 12 x 16B segments per thread per stage ----
    const __nv_bfloat16* src[12];
    uint32_t dst[12];
#pragma unroll
    for (int j = 0; j < 12; j++) {
        int gid = tid + j * 256;
        if (gid < 1024) {                       // A (hi then lo)
            int mat = gid >> 9;
            int idx = gid & 511;
            int row = idx >> 2, ks = idx & 3;
            int rr = m0 + row; if (rr > cnt - 1) rr = cnt - 1;
            if (WHICH == 1) {
                int tokid = g_pairTok[e * TOK + rr];
                src[j] = (mat ? g_xl : g_xh) + (size_t)tokid * DDIM + ks * 8;
            } else {
                src[j] = (mat ? g_al : g_ah) + ((size_t)e * TOK + rr) * DDIM + ks * 8;
            }
            dst[j] = (mat ? AL_OFF : AH_OFF) + row * 80 + ks * 16;
        } else {                                // B (hi then lo)
            int g2  = gid - 1024;
            int mat = g2 >> 10;
            int idx = g2 & 1023;
            int row = idx >> 2, ks = idx & 3;
            src[j] = (mat ? wtL : wtH) + ((size_t)e * DDIM + n0 + row) * DDIM + ks * 8;
            dst[j] = (mat ? BL_OFF : BH_OFF) + row * 80 + ks * 16;
        }
    }

    auto issue = [&](int chunk, int s) {
        const int k0 = chunk * BK;
        const uint32_t sb = sbase + s * STAGE_B;
#pragma unroll
        for (int j = 0; j < 12; j++) cp16(sb + dst[j], src[j] + k0);
    };

    // warp layout: warp_m = wid>>2 (64 rows), warp_n = wid&3 (64 cols)
    const int warp_m = wid >> 2;
    const int warp_n = wid & 3;
    const int l15 = lane & 15;
    const uint32_t aoff = (uint32_t)((warp_m * 64 + l15) * 80 + (lane >> 4) * 16);
    const uint32_t boff = (uint32_t)((warp_n * 64 + (lane >> 4) * 8 + (lane & 7)) * 80 +
                                     ((lane >> 3) & 1) * 16);

    float acc[4][8][4];
#pragma unroll
    for (int mt = 0; mt < 4; mt++)
#pragma unroll
        for (int nt = 0; nt < 8; nt++)
#pragma unroll
            for (int q = 0; q < 4; q++) acc[mt][nt][q] = 0.f;

    issue(0, 0); CP_COMMIT();
    issue(1, 1); CP_COMMIT();

    for (int i = 0; i < NCHUNK; i++) {
        const int s = i % NSTAGE;
        CP_WAIT1();
        __syncthreads();
        if (i + 2 < NCHUNK) issue(i + 2, (i + 2) % NSTAGE);
        CP_COMMIT();

        const uint32_t sb = sbase + s * STAGE_B;
        const uint32_t aH = sb + AH_OFF + aoff;
        const uint32_t aL = sb + AL_OFF + aoff;
        const uint32_t bH = sb + BH_OFF + boff;
        const uint32_t bL = sb + BL_OFF + boff;
#pragma unroll
        for (int k16 = 0; k16 < 2; k16++) {
            uint32_t bh[8][2], bl[8][2];
#pragma unroll
            for (int p = 0; p < 4; p++) {
                uint32_t r4[4];
                ldsm4(r4, bH + p * 16 * 80 + k16 * 32);
                bh[2 * p][0] = r4[0]; bh[2 * p][1] = r4[1];
                bh[2 * p + 1][0] = r4[2]; bh[2 * p + 1][1] = r4[3];
                ldsm4(r4, bL + p * 16 * 80 + k16 * 32);
                bl[2 * p][0] = r4[0]; bl[2 * p][1] = r4[1];
                bl[2 * p + 1][0] = r4[2]; bl[2 * p + 1][1] = r4[3];
            }
#pragma unroll
            for (int mt = 0; mt < 4; mt++) {
                uint32_t ah[4], al[4];
                ldsm4(ah, aH + mt * 16 * 80 + k16 * 32);
                ldsm4(al, aL + mt * 16 * 80 + k16 * 32);
#pragma unroll
                for (int nt = 0; nt < 8; nt++) {
                    mma16816(acc[mt][nt], ah, bh[nt]);
                    mma16816(acc[mt][nt], ah, bl[nt]);
                    mma16816(acc[mt][nt], al, bh[nt]);
                }
            }
        }
    }

    // ---- epilogue: bias add + fp32 store ----
    const int groupid = lane >> 2;
    const int t4      = lane & 3;
    float2 bv[8];
#pragma unroll
    for (int nt = 0; nt < 8; nt++)
        bv[nt] = *(const float2*)(bias + (size_t)e * DDIM + n0 + warp_n * 64 + nt * 8 + t4 * 2);

    float* OutB = (WHICH == 1) ? g_h1 : g_h2;
#pragma unroll
    for (int mt = 0; mt < 4; mt++) {
        int r0 = m0 + warp_m * 64 + mt * 16 + groupid;
        int r1 = r0 + 8;
        float* p0 = OutB + ((size_t)e * TOK + r0) * DDIM + n0 + warp_n * 64 + t4 * 2;
        float* p1 = OutB + ((size_t)e * TOK + r1) * DDIM + n0 + warp_n * 64 + t4 * 2;
#pragma unroll
        for (int nt = 0; nt < 8; nt++) {
            if (r0 < cnt)
                *(float2*)(p0 + nt * 8) = make_float2(acc[mt][nt][0] + bv[nt].x,
                                                      acc[mt][nt][1] + bv[nt].y);
            if (r1 < cnt)
                *(float2*)(p1 + nt * 8) = make_float2(acc[mt][nt][2] + bv[nt].x,
                                                      acc[mt][nt][3] + bv[nt].y);
        }
    }
}

// ---------------------------------------------------------------------------
// 3) LN1 + relu: reads g_h1 fp32, writes bf16 hi/lo into g_ah/g_al
// ---------------------------------------------------------------------------
__global__ void ln1_kernel(const float* __restrict__ w,
                           const float* __restrict__ b) {
    int gw = (blockIdx.x * blockDim.x + threadIdx.x) >> 5;
    int e   = gw >> 15;
    int pos = gw & (TOK - 1);
    if (pos >= g_cnt[e]) return;
    int lane = threadIdx.x & 31;
    const float* row = g_h1 + (size_t)gw * DDIM;

    float v[16];
    float s = 0.f;
#pragma unroll
    for (int i = 0; i < 16; i++) { v[i] = row[lane + i * 32]; s += v[i]; }
#pragma unroll
    for (int o = 16; o > 0; o >>= 1) s += __shfl_xor_sync(0xffffffffu, s, o);
    float mu = s * (1.f / DDIM);

    float q = 0.f;
#pragma unroll
    for (int i = 0; i < 16; i++) { float d = v[i] - mu; q += d * d; }
#pragma unroll
    for (int o = 16; o > 0; o >>= 1) q += __shfl_xor_sync(0xffffffffu, q, o);
    float rstd = rsqrtf(q * (1.f / DDIM) + LN_EPS);

    const float* we = w + e * DDIM;
    const float* be = b + e * DDIM;
    __nv_bfloat16* oh = g_ah + (size_t)gw * DDIM;
    __nv_bfloat16* ol = g_al + (size_t)gw * DDIM;
#pragma unroll
    for (int i = 0; i < 16; i++) {
        int d = lane + i * 32;
        float y = fmaxf((v[i] - mu) * rstd * we[d] + be[d], 0.f);
        __nv_bfloat16 h = __float2bfloat16(y);
        oh[d] = h;
        ol[d] = __float2bfloat16(y - __bfloat162float(h));
    }
}

// ---------------------------------------------------------------------------
// 6) combine + fused LN2: warp per token; 4 rows of g_h2 (pre-LN), LN inline
// ---------------------------------------------------------------------------
__global__ void combine_kernel(const float* __restrict__ x,
                               const float* __restrict__ lnw,
                               const float* __restrict__ lnb,
                               float* __restrict__ out) {
    int gw   = (blockIdx.x * blockDim.x + threadIdx.x) >> 5;
    int lane = threadIdx.x & 31;
    const int t = gw;

    int   pr[4];
    float wt[4];
#pragma unroll
    for (int j = 0; j < 4; j++) {
        pr[j] = g_tokPair[t * 4 + j];
        wt[j] = g_tokW[t * 4 + j];
    }

    float v[4][16];
    float mu[4], rs[4];
#pragma unroll
    for (int r = 0; r < 4; r++) {
        const float* row = g_h2 + (size_t)pr[r] * DDIM;
        float s = 0.f;
#pragma unroll
        for (int i = 0; i < 16; i++) { v[r][i] = row[lane + i * 32]; s += v[r][i]; }
#pragma unroll
        for (int o = 16; o > 0; o >>= 1) s += __shfl_xor_sync(0xffffffffu, s, o);
        mu[r] = s * (1.f / DDIM);
        float q = 0.f;
#pragma unroll
        for (int i = 0; i < 16; i++) { float d = v[r][i] - mu[r]; q += d * d; }
#pragma unroll
        for (int o = 16; o > 0; o >>= 1) q += __shfl_xor_sync(0xffffffffu, q, o);
        rs[r] = rsqrtf(q * (1.f / DDIM) + LN_EPS);
    }

    const float* lw[4];
    const float* lb[4];
#pragma unroll
    for (int r = 0; r < 4; r++) {
        int e = pr[r] >> 15;           // / TOK
        lw[r] = lnw + (size_t)e * DDIM;
        lb[r] = lnb + (size_t)e * DDIM;
    }

    const float* xr = x + (size_t)t * DDIM;
    float* o_out = out + (size_t)t * DDIM;
    float* o_top = out + (size_t)BND + (size_t)t * DDIM;
    float* o_bot = out + 2 * (size_t)BND + (size_t)t * DDIM;

    float accd = 0.f;
#pragma unroll
    for (int i = 0; i < 16; i++) {
        int d = lane + i * 32;
        float ya = (v[0][i] - mu[0]) * rs[0] * lw[0][d] + lb[0][d];
        float yb = (v[1][i] - mu[1]) * rs[1] * lw[1][d] + lb[1][d];
        float yc = (v[2][i] - mu[2]) * rs[2] * lw[2][d] + lb[2][d];
        float yd = (v[3][i] - mu[3]) * rs[3] * lw[3][d] + lb[3][d];
        float top = wt[0] * ya + wt[1] * yb;
        float bot = wt[2] * yc + wt[3] * yd;
        o_top[d] = top;
        o_bot[d] = bot;
        o_out[d] = top + xr[d];
        float df = top - bot;
        accd += df * df;
    }
#pragma unroll
    for (int o = 16; o > 0; o >>= 1) accd += __shfl_xor_sync(0xffffffffu, accd, o);

    __shared__ float red[8];
    if (lane == 0) red[threadIdx.x >> 5] = accd;
    __syncthreads();
    if (threadIdx.x == 0) {
        float ssum = 0.f;
        for (int i = 0; i < 8; i++) ssum += red[i];
        g_part[blockIdx.x] = ssum;
    }
}

// ---------------------------------------------------------------------------
// 7) loss
// ---------------------------------------------------------------------------
__global__ void loss_kernel(float* __restrict__ out) {
    int w = threadIdx.x >> 5, lane = threadIdx.x & 31;
    __shared__ float lred[8];
    float s = 0.f;
    for (int i = lane; i < 512; i += 32) s += g_part[w * 512 + i];
#pragma unroll
    for (int o = 16; o > 0; o >>= 1) s += __shfl_xor_sync(0xffffffffu, s, o);
    if (lane == 0) lred[w] = 1.f / (sqrtf(s) + 1e-8f);
    __syncthreads();
    if (threadIdx.x == 0) {
        float a = 0.f;
        for (int i = 0; i < 8; i++) a += lred[i];
        out[(size_t)3 * BND] = a * (1.f / 8.f);
    }
}

// ---------------------------------------------------------------------------
// launch
// ---------------------------------------------------------------------------
extern "C" void kernel_launch(void* const* d_in, const int* in_sizes, int n_in,
                              void* d_out, int out_size) {
    const float* x    = (const float*)d_in[0];
    const float* Wg   = (const float*)d_in[1];
    const float* bg   = (const float*)d_in[2];
    const float* W1   = (const float*)d_in[3];
    const float* b1   = (const float*)d_in[4];
    const float* ln1w = (const float*)d_in[5];
    const float* ln1b = (const float*)d_in[6];
    const float* W2   = (const float*)d_in[7];
    const float* b2   = (const float*)d_in[8];
    const float* ln2w = (const float*)d_in[9];
    const float* ln2b = (const float*)d_in[10];
    float* out = (float*)d_out;

    static int smem_set = 0;
    if (!smem_set) {
        cudaFuncSetAttribute(gemm_mma<1>, cudaFuncAttributeMaxDynamicSharedMemorySize, SMEM_DYN);
        cudaFuncSetAttribute(gemm_mma<2>, cudaFuncAttributeMaxDynamicSharedMemorySize, SMEM_DYN);
        smem_set = 1;
    }

    init_kernel<<<1, 32>>>();
    gating_kernel<<<TOK * 32 / 256, 256>>>(x, Wg, bg);

    dim3 wgrid(DDIM / 32, DDIM / 32, NEXP);
    wconv_kernel<1><<<wgrid, dim3(32, 8)>>>(W1);
    wconv_kernel<2><<<wgrid, dim3(32, 8)>>>(W2);

    dim3 ggrid(DDIM / BN, TOK / BM, NEXP);   // (2, 256, 8)
    gemm_mma<1><<<ggrid, 256, SMEM_DYN>>>(b1);
    ln1_kernel<<<NEXP * TOK * 32 / 256, 256>>>(ln1w, ln1b);
    gemm_mma<2><<<ggrid, 256, SMEM_DYN>>>(b2);
    ln2_dummy: ;
    combine_kernel<<<TOK * 32 / 256, 256>>>(x, ln2w, ln2b, out);
    loss_kernel<<<1, 256>>>(out);
}

// round 6
// speedup vs baseline: 2.8096x; 1.2921x over previous
#include <cuda_runtime.h>
#include <cuda_fp16.h>
#include <math.h>
#include <stdint.h>

// Problem constants
#define TOK   32768          // B*N = 8*4096
#define NEXP  8
#define DDIM  512
#define BND   16777216       // TOK * DDIM
#define LN_EPS 1e-5f

// GEMM tile config (fp16 2-term: D = Ah*Bm + Al*Bm, A split hi/lo, B rounded)
#define BM 128
#define BN 256
#define BK 32
#define NCHUNK (DDIM / BK)   // 16
// smem stage layout (bytes): rows padded to 40 fp16 = 80B (conflict-free ldsm)
#define AH_OFF 0
#define AL_OFF 10240
#define B_OFF  20480
#define STAGE_B 40960
#define NSTAGE 3
#define SMEM_DYN (NSTAGE * STAGE_B)   // 122880

// ---------------------------------------------------------------------------
// Scratch (__device__ globals; no allocations allowed)
// ---------------------------------------------------------------------------
__device__ int   g_cnt[NEXP];
__device__ int   g_pairTok[NEXP * TOK];
__device__ int   g_tokPair[TOK * 4];
__device__ float g_tokW[TOK * 4];
__device__ float g_h1[(size_t)NEXP * TOK * DDIM];
__device__ float g_h2[(size_t)NEXP * TOK * DDIM];
__device__ float g_part[4096];
__device__ __half g_xh[(size_t)TOK * DDIM];          // x split hi (token space)
__device__ __half g_xl[(size_t)TOK * DDIM];          // x split lo
__device__ __half g_ah[(size_t)NEXP * TOK * DDIM];   // ln1 out hi (pair space)
__device__ __half g_al[(size_t)NEXP * TOK * DDIM];   // ln1 out lo
__device__ __half g_w1t[(size_t)NEXP * DDIM * DDIM]; // W1^T fp16
__device__ __half g_w2t[(size_t)NEXP * DDIM * DDIM]; // W2^T fp16

// ---------------------------------------------------------------------------
// Helpers
// ---------------------------------------------------------------------------
__device__ __forceinline__ uint32_t smem_u32(const void* p) {
    uint32_t a;
    asm("{ .reg .u64 t; cvta.to.shared.u64 t, %1; cvt.u32.u64 %0, t; }" : "=r"(a) : "l"(p));
    return a;
}
__device__ __forceinline__ void cp16(uint32_t dst, const void* src) {
    asm volatile("cp.async.cg.shared.global [%0], [%1], 16;" :: "r"(dst), "l"(src));
}
#define CP_COMMIT() asm volatile("cp.async.commit_group;" ::: "memory")
#define CP_WAIT1()  asm volatile("cp.async.wait_group 1;" ::: "memory")
__device__ __forceinline__ void ldsm4(uint32_t* r, uint32_t addr) {
    asm volatile("ldmatrix.sync.aligned.m8n8.x4.shared.b16 {%0,%1,%2,%3}, [%4];"
                 : "=r"(r[0]), "=r"(r[1]), "=r"(r[2]), "=r"(r[3]) : "r"(addr));
}
__device__ __forceinline__ void mma16816(float* c, const uint32_t* a, const uint32_t* b) {
    asm volatile(
        "mma.sync.aligned.m16n8k16.row.col.f32.f16.f16.f32 "
        "{%0,%1,%2,%3}, {%4,%5,%6,%7}, {%8,%9}, {%0,%1,%2,%3};"
        : "+f"(c[0]), "+f"(c[1]), "+f"(c[2]), "+f"(c[3])
        : "r"(a[0]), "r"(a[1]), "r"(a[2]), "r"(a[3]), "r"(b[0]), "r"(b[1]));
}

// ---------------------------------------------------------------------------
// 0) zero counters
// ---------------------------------------------------------------------------
__global__ void init_kernel() {
    if (threadIdx.x < NEXP) g_cnt[threadIdx.x] = 0;
}

// ---------------------------------------------------------------------------
// 1) gating: scores + routing + x fp16 hi/lo split (token space)
// ---------------------------------------------------------------------------
__global__ void gating_kernel(const float* __restrict__ x,
                              const float* __restrict__ Wg,
                              const float* __restrict__ bg) {
    int gw = (blockIdx.x * blockDim.x + threadIdx.x) >> 5;
    if (gw >= TOK) return;
    int lane = threadIdx.x & 31;
    const float* xr = x + (size_t)gw * DDIM;
    __half* xh = g_xh + (size_t)gw * DDIM;
    __half* xl = g_xl + (size_t)gw * DDIM;

    float s[NEXP];
#pragma unroll
    for (int e = 0; e < NEXP; e++) s[e] = 0.f;
#pragma unroll
    for (int i = 0; i < 16; i++) {
        int d = lane + i * 32;
        float xv = xr[d];
        const float* wr = Wg + d * NEXP;
#pragma unroll
        for (int e = 0; e < NEXP; e++) s[e] += xv * wr[e];
        __half h = __float2half_rn(xv);
        xh[d] = h;
        xl[d] = __float2half_rn(xv - __half2float(h));
    }
#pragma unroll
    for (int e = 0; e < NEXP; e++) {
#pragma unroll
        for (int o = 16; o > 0; o >>= 1)
            s[e] += __shfl_xor_sync(0xffffffffu, s[e], o);
    }
    if (lane == 0) {
#pragma unroll
        for (int e = 0; e < NEXP; e++) s[e] += bg[e];
        int i0 = 0; float v0 = s[0];
        for (int e = 1; e < NEXP; e++) if (s[e] > v0) { v0 = s[e]; i0 = e; }
        int i1 = -1; float v1 = -1e30f;
        for (int e = 0; e < NEXP; e++) if (e != i0 && s[e] > v1) { v1 = s[e]; i1 = e; }
        int j0 = 0; float u0 = s[0];
        for (int e = 1; e < NEXP; e++) if (s[e] < u0) { u0 = s[e]; j0 = e; }
        int j1 = -1; float u1 = 1e30f;
        for (int e = 0; e < NEXP; e++) if (e != j0 && s[e] < u1) { u1 = s[e]; j1 = e; }

        float et  = expf(v1 - v0);
        float wt0 = 1.f / (1.f + et);
        float wt1 = et * wt0;
        float eb  = expf(u0 - u1);
        float wb1 = 1.f / (1.f + eb);
        float wb0 = eb * wb1;

        int p;
        p = atomicAdd(&g_cnt[i0], 1);
        g_pairTok[i0 * TOK + p] = gw;
        g_tokPair[gw * 4 + 0] = i0 * TOK + p;  g_tokW[gw * 4 + 0] = wt0;
        p = atomicAdd(&g_cnt[i1], 1);
        g_pairTok[i1 * TOK + p] = gw;
        g_tokPair[gw * 4 + 1] = i1 * TOK + p;  g_tokW[gw * 4 + 1] = wt1;
        p = atomicAdd(&g_cnt[j0], 1);
        g_pairTok[j0 * TOK + p] = gw;
        g_tokPair[gw * 4 + 2] = j0 * TOK + p;  g_tokW[gw * 4 + 2] = wb0;
        p = atomicAdd(&g_cnt[j1], 1);
        g_pairTok[j1 * TOK + p] = gw;
        g_tokPair[gw * 4 + 3] = j1 * TOK + p;  g_tokW[gw * 4 + 3] = wb1;
    }
}

// ---------------------------------------------------------------------------
// 1b) weight prep: W[e][k][n] fp32 -> Wt[e][n][k] fp16 (transpose + round)
// ---------------------------------------------------------------------------
template <int WHICH>
__global__ void wconv_kernel(const float* __restrict__ W) {
    __shared__ float t[32][33];
    int e  = blockIdx.z;
    int kb = blockIdx.x * 32, nb = blockIdx.y * 32;
    const float* src = W + (size_t)e * DDIM * DDIM;
    int tx = threadIdx.x, ty = threadIdx.y;
#pragma unroll
    for (int r = ty; r < 32; r += 8)
        t[r][tx] = src[(size_t)(kb + r) * DDIM + nb + tx];
    __syncthreads();
    __half* T = (WHICH == 1) ? g_w1t : g_w2t;
#pragma unroll
    for (int r = ty; r < 32; r += 8) {
        float v = t[tx][r];  // = W[kb+tx][nb+r]
        T[((size_t)e * DDIM + (nb + r)) * DDIM + kb + tx] = __float2half_rn(v);
    }
}

// ---------------------------------------------------------------------------
// 2/4) fp16 2-term HMMA GEMM, cp.async 3-stage pipeline.
//      BM=128, BN=256, BK=32; 256 threads = 8 warps (2 x 4), warp tile 64x64.
//      WHICH=1: A = g_xh/g_xl gathered via pairTok; out g_h1.
//      WHICH=2: A = g_ah/g_al pair-space (ln1 out); out g_h2.
// ---------------------------------------------------------------------------
template <int WHICH>
__global__ void __launch_bounds__(256, 1) gemm_mma(const float* __restrict__ bias) {
    const int e   = blockIdx.z;
    const int cnt = g_cnt[e];
    const int m0  = blockIdx.y * BM;
    if (m0 >= cnt) return;
    const int n0  = blockIdx.x * BN;

    extern __shared__ char dsm[];
    const uint32_t sbase = smem_u32(dsm);

    const int tid  = threadIdx.x;
    const int wid  = tid >> 5;
    const int lane = tid & 31;

    const __half* wt = (WHICH == 1) ? g_w1t : g_w2t;

    // ---- loader precompute: 8 x 16B segments per thread per stage ----
    const __half* src[8];
    uint32_t dst[8];
#pragma unroll
    for (int j = 0; j < 8; j++) {
        int gid = tid + j * 256;
        if (gid < 1024) {                       // A (hi then lo)
            int mat = gid >> 9;
            int idx = gid & 511;
            int row = idx >> 2, ks = idx & 3;
            int rr = m0 + row; if (rr > cnt - 1) rr = cnt - 1;
            if (WHICH == 1) {
                int tokid = g_pairTok[e * TOK + rr];
                src[j] = (mat ? g_xl : g_xh) + (size_t)tokid * DDIM + ks * 8;
            } else {
                src[j] = (mat ? g_al : g_ah) + ((size_t)e * TOK + rr) * DDIM + ks * 8;
            }
            dst[j] = (mat ? AL_OFF : AH_OFF) + row * 80 + ks * 16;
        } else {                                // B (single fp16)
            int idx = gid - 1024;               // 0..1023
            int row = idx >> 2, ks = idx & 3;
            src[j] = wt + ((size_t)e * DDIM + n0 + row) * DDIM + ks * 8;
            dst[j] = B_OFF + row * 80 + ks * 16;
        }
    }

    auto issue = [&](int chunk, int s) {
        const int k0 = chunk * BK;
        const uint32_t sb = sbase + s * STAGE_B;
#pragma unroll
        for (int j = 0; j < 8; j++) cp16(sb + dst[j], src[j] + k0);
    };

    // warp layout: warp_m = wid>>2 (64 rows), warp_n = wid&3 (64 cols)
    const int warp_m = wid >> 2;
    const int warp_n = wid & 3;
    const int l15 = lane & 15;
    const uint32_t aoff = (uint32_t)((warp_m * 64 + l15) * 80 + (lane >> 4) * 16);
    const uint32_t boff = (uint32_t)((warp_n * 64 + (lane >> 4) * 8 + (lane & 7)) * 80 +
                                     ((lane >> 3) & 1) * 16);

    float acc[4][8][4];
#pragma unroll
    for (int mt = 0; mt < 4; mt++)
#pragma unroll
        for (int nt = 0; nt < 8; nt++)
#pragma unroll
            for (int q = 0; q < 4; q++) acc[mt][nt][q] = 0.f;

    issue(0, 0); CP_COMMIT();
    issue(1, 1); CP_COMMIT();

    for (int i = 0; i < NCHUNK; i++) {
        const int s = i % NSTAGE;
        CP_WAIT1();
        __syncthreads();
        if (i + 2 < NCHUNK) issue(i + 2, (i + 2) % NSTAGE);
        CP_COMMIT();

        const uint32_t sb = sbase + s * STAGE_B;
        const uint32_t aH = sb + AH_OFF + aoff;
        const uint32_t aL = sb + AL_OFF + aoff;
        const uint32_t bB = sb + B_OFF + boff;
#pragma unroll
        for (int k16 = 0; k16 < 2; k16++) {
            uint32_t bh[8][2];
#pragma unroll
            for (int p = 0; p < 4; p++) {
                uint32_t r4[4];
                ldsm4(r4, bB + p * 16 * 80 + k16 * 32);
                bh[2 * p][0] = r4[0]; bh[2 * p][1] = r4[1];
                bh[2 * p + 1][0] = r4[2]; bh[2 * p + 1][1] = r4[3];
            }
#pragma unroll
            for (int mt = 0; mt < 4; mt++) {
                uint32_t ah[4], al[4];
                ldsm4(ah, aH + mt * 16 * 80 + k16 * 32);
                ldsm4(al, aL + mt * 16 * 80 + k16 * 32);
#pragma unroll
                for (int nt = 0; nt < 8; nt++) {
                    mma16816(acc[mt][nt], ah, bh[nt]);
                    mma16816(acc[mt][nt], al, bh[nt]);
                }
            }
        }
    }

    // ---- epilogue: bias add + fp32 store ----
    const int groupid = lane >> 2;
    const int t4      = lane & 3;
    float2 bv[8];
#pragma unroll
    for (int nt = 0; nt < 8; nt++)
        bv[nt] = *(const float2*)(bias + (size_t)e * DDIM + n0 + warp_n * 64 + nt * 8 + t4 * 2);

    float* OutB = (WHICH == 1) ? g_h1 : g_h2;
#pragma unroll
    for (int mt = 0; mt < 4; mt++) {
        int r0 = m0 + warp_m * 64 + mt * 16 + groupid;
        int r1 = r0 + 8;
        float* p0 = OutB + ((size_t)e * TOK + r0) * DDIM + n0 + warp_n * 64 + t4 * 2;
        float* p1 = OutB + ((size_t)e * TOK + r1) * DDIM + n0 + warp_n * 64 + t4 * 2;
#pragma unroll
        for (int nt = 0; nt < 8; nt++) {
            if (r0 < cnt)
                *(float2*)(p0 + nt * 8) = make_float2(acc[mt][nt][0] + bv[nt].x,
                                                      acc[mt][nt][1] + bv[nt].y);
            if (r1 < cnt)
                *(float2*)(p1 + nt * 8) = make_float2(acc[mt][nt][2] + bv[nt].x,
                                                      acc[mt][nt][3] + bv[nt].y);
        }
    }
}

// ---------------------------------------------------------------------------
// 3) LN1 + relu: reads g_h1 fp32, writes fp16 hi/lo into g_ah/g_al
// ---------------------------------------------------------------------------
__global__ void ln1_kernel(const float* __restrict__ w,
                           const float* __restrict__ b) {
    int gw = (blockIdx.x * blockDim.x + threadIdx.x) >> 5;
    int e   = gw >> 15;
    int pos = gw & (TOK - 1);
    if (pos >= g_cnt[e]) return;
    int lane = threadIdx.x & 31;
    const float* row = g_h1 + (size_t)gw * DDIM;

    float v[16];
    float s = 0.f;
#pragma unroll
    for (int i = 0; i < 16; i++) { v[i] = row[lane + i * 32]; s += v[i]; }
#pragma unroll
    for (int o = 16; o > 0; o >>= 1) s += __shfl_xor_sync(0xffffffffu, s, o);
    float mu = s * (1.f / DDIM);

    float q = 0.f;
#pragma unroll
    for (int i = 0; i < 16; i++) { float d = v[i] - mu; q += d * d; }
#pragma unroll
    for (int o = 16; o > 0; o >>= 1) q += __shfl_xor_sync(0xffffffffu, q, o);
    float rstd = rsqrtf(q * (1.f / DDIM) + LN_EPS);

    const float* we = w + e * DDIM;
    const float* be = b + e * DDIM;
    __half* oh = g_ah + (size_t)gw * DDIM;
    __half* ol = g_al + (size_t)gw * DDIM;
#pragma unroll
    for (int i = 0; i < 16; i++) {
        int d = lane + i * 32;
        float y = fmaxf((v[i] - mu) * rstd * we[d] + be[d], 0.f);
        __half h = __float2half_rn(y);
        oh[d] = h;
        ol[d] = __float2half_rn(y - __half2float(h));
    }
}

// ---------------------------------------------------------------------------
// 6) combine + fused LN2: warp per token; 4 rows of g_h2 (pre-LN), LN inline
// ---------------------------------------------------------------------------
__global__ void combine_kernel(const float* __restrict__ x,
                               const float* __restrict__ lnw,
                               const float* __restrict__ lnb,
                               float* __restrict__ out) {
    int gw   = (blockIdx.x * blockDim.x + threadIdx.x) >> 5;
    int lane = threadIdx.x & 31;
    const int t = gw;

    int   pr[4];
    float wt[4];
#pragma unroll
    for (int j = 0; j < 4; j++) {
        pr[j] = g_tokPair[t * 4 + j];
        wt[j] = g_tokW[t * 4 + j];
    }

    float v[4][16];
    float mu[4], rs[4];
#pragma unroll
    for (int r = 0; r < 4; r++) {
        const float* row = g_h2 + (size_t)pr[r] * DDIM;
        float s = 0.f;
#pragma unroll
        for (int i = 0; i < 16; i++) { v[r][i] = row[lane + i * 32]; s += v[r][i]; }
#pragma unroll
        for (int o = 16; o > 0; o >>= 1) s += __shfl_xor_sync(0xffffffffu, s, o);
        mu[r] = s * (1.f / DDIM);
        float q = 0.f;
#pragma unroll
        for (int i = 0; i < 16; i++) { float d = v[r][i] - mu[r]; q += d * d; }
#pragma unroll
        for (int o = 16; o > 0; o >>= 1) q += __shfl_xor_sync(0xffffffffu, q, o);
        rs[r] = rsqrtf(q * (1.f / DDIM) + LN_EPS);
    }

    const float* lw[4];
    const float* lb[4];
#pragma unroll
    for (int r = 0; r < 4; r++) {
        int e = pr[r] >> 15;           // / TOK
        lw[r] = lnw + (size_t)e * DDIM;
        lb[r] = lnb + (size_t)e * DDIM;
    }

    const float* xr = x + (size_t)t * DDIM;
    float* o_out = out + (size_t)t * DDIM;
    float* o_top = out + (size_t)BND + (size_t)t * DDIM;
    float* o_bot = out + 2 * (size_t)BND + (size_t)t * DDIM;

    float accd = 0.f;
#pragma unroll
    for (int i = 0; i < 16; i++) {
        int d = lane + i * 32;
        float ya = (v[0][i] - mu[0]) * rs[0] * lw[0][d] + lb[0][d];
        float yb = (v[1][i] - mu[1]) * rs[1] * lw[1][d] + lb[1][d];
        float yc = (v[2][i] - mu[2]) * rs[2] * lw[2][d] + lb[2][d];
        float yd = (v[3][i] - mu[3]) * rs[3] * lw[3][d] + lb[3][d];
        float top = wt[0] * ya + wt[1] * yb;
        float bot = wt[2] * yc + wt[3] * yd;
        o_top[d] = top;
        o_bot[d] = bot;
        o_out[d] = top + xr[d];
        float df = top - bot;
        accd += df * df;
    }
#pragma unroll
    for (int o = 16; o > 0; o >>= 1) accd += __shfl_xor_sync(0xffffffffu, accd, o);

    __shared__ float red[8];
    if (lane == 0) red[threadIdx.x >> 5] = accd;
    __syncthreads();
    if (threadIdx.x == 0) {
        float ssum = 0.f;
        for (int i = 0; i < 8; i++) ssum += red[i];
        g_part[blockIdx.x] = ssum;
    }
}

// ---------------------------------------------------------------------------
// 7) loss
// ---------------------------------------------------------------------------
__global__ void loss_kernel(float* __restrict__ out) {
    int w = threadIdx.x >> 5, lane = threadIdx.x & 31;
    __shared__ float lred[8];
    float s = 0.f;
    for (int i = lane; i < 512; i += 32) s += g_part[w * 512 + i];
#pragma unroll
    for (int o = 16; o > 0; o >>= 1) s += __shfl_xor_sync(0xffffffffu, s, o);
    if (lane == 0) lred[w] = 1.f / (sqrtf(s) + 1e-8f);
    __syncthreads();
    if (threadIdx.x == 0) {
        float a = 0.f;
        for (int i = 0; i < 8; i++) a += lred[i];
        out[(size_t)3 * BND] = a * (1.f / 8.f);
    }
}

// ---------------------------------------------------------------------------
// launch
// ---------------------------------------------------------------------------
extern "C" void kernel_launch(void* const* d_in, const int* in_sizes, int n_in,
                              void* d_out, int out_size) {
    const float* x    = (const float*)d_in[0];
    const float* Wg   = (const float*)d_in[1];
    const float* bg   = (const float*)d_in[2];
    const float* W1   = (const float*)d_in[3];
    const float* b1   = (const float*)d_in[4];
    const float* ln1w = (const float*)d_in[5];
    const float* ln1b = (const float*)d_in[6];
    const float* W2   = (const float*)d_in[7];
    const float* b2   = (const float*)d_in[8];
    const float* ln2w = (const float*)d_in[9];
    const float* ln2b = (const float*)d_in[10];
    float* out = (float*)d_out;

    static int smem_set = 0;
    if (!smem_set) {
        cudaFuncSetAttribute(gemm_mma<1>, cudaFuncAttributeMaxDynamicSharedMemorySize, SMEM_DYN);
        cudaFuncSetAttribute(gemm_mma<2>, cudaFuncAttributeMaxDynamicSharedMemorySize, SMEM_DYN);
        smem_set = 1;
    }

    init_kernel<<<1, 32>>>();
    gating_kernel<<<TOK * 32 / 256, 256>>>(x, Wg, bg);

    dim3 wgrid(DDIM / 32, DDIM / 32, NEXP);
    wconv_kernel<1><<<wgrid, dim3(32, 8)>>>(W1);
    wconv_kernel<2><<<wgrid, dim3(32, 8)>>>(W2);

    dim3 ggrid(DDIM / BN, TOK / BM, NEXP);   // (2, 256, 8)
    gemm_mma<1><<<ggrid, 256, SMEM_DYN>>>(b1);
    ln1_kernel<<<NEXP * TOK * 32 / 256, 256>>>(ln1w, ln1b);
    gemm_mma<2><<<ggrid, 256, SMEM_DYN>>>(b2);
    combine_kernel<<<TOK * 32 / 256, 256>>>(x, ln2w, ln2b, out);
    loss_kernel<<<1, 256>>>(out);
}

// round 7
// speedup vs baseline: 2.9196x; 1.0392x over previous
#include <cuda_runtime.h>
#include <cuda_fp16.h>
#include <math.h>
#include <stdint.h>

// Problem constants
#define TOK   32768          // B*N = 8*4096
#define NEXP  8
#define DDIM  512
#define BND   16777216       // TOK * DDIM
#define LN_EPS 1e-5f

// GEMM tile config (fp16 2-term: D = Ah*Bm + Al*Bm, A split hi/lo, B rounded)
#define BM 128
#define BN 256
#define BK 32
#define NCHUNK (DDIM / BK)   // 16
// smem stage layout (bytes): rows padded to 40 fp16 = 80B (conflict-free ldsm)
#define AH_OFF 0
#define AL_OFF 10240
#define B_OFF  20480
#define STAGE_B 40960
#define NSTAGE 3
#define SMEM_DYN (NSTAGE * STAGE_B)   // 122880

// ---------------------------------------------------------------------------
// Scratch (__device__ globals; no allocations allowed)
// ---------------------------------------------------------------------------
__device__ int   g_cnt[NEXP];
__device__ int   g_pairTok[NEXP * TOK];
__device__ int   g_tokPair[TOK * 4];
__device__ float g_tokW[TOK * 4];
__device__ __half g_h1[(size_t)NEXP * TOK * DDIM];   // GEMM1 out (pre-LN1), fp16
__device__ __half g_h2[(size_t)NEXP * TOK * DDIM];   // GEMM2 out (pre-LN2), fp16
__device__ float g_part[4096];
__device__ __half g_xh[(size_t)TOK * DDIM];          // x split hi (token space)
__device__ __half g_xl[(size_t)TOK * DDIM];          // x split lo
__device__ __half g_ah[(size_t)NEXP * TOK * DDIM];   // ln1 out hi (pair space)
__device__ __half g_al[(size_t)NEXP * TOK * DDIM];   // ln1 out lo
__device__ __half g_w1t[(size_t)NEXP * DDIM * DDIM]; // W1^T fp16
__device__ __half g_w2t[(size_t)NEXP * DDIM * DDIM]; // W2^T fp16

// ---------------------------------------------------------------------------
// Helpers
// ---------------------------------------------------------------------------
__device__ __forceinline__ uint32_t smem_u32(const void* p) {
    uint32_t a;
    asm("{ .reg .u64 t; cvta.to.shared.u64 t, %1; cvt.u32.u64 %0, t; }" : "=r"(a) : "l"(p));
    return a;
}
__device__ __forceinline__ void cp16(uint32_t dst, const void* src) {
    asm volatile("cp.async.cg.shared.global [%0], [%1], 16;" :: "r"(dst), "l"(src));
}
#define CP_COMMIT() asm volatile("cp.async.commit_group;" ::: "memory")
#define CP_WAIT1()  asm volatile("cp.async.wait_group 1;" ::: "memory")
__device__ __forceinline__ void ldsm4(uint32_t* r, uint32_t addr) {
    asm volatile("ldmatrix.sync.aligned.m8n8.x4.shared.b16 {%0,%1,%2,%3}, [%4];"
                 : "=r"(r[0]), "=r"(r[1]), "=r"(r[2]), "=r"(r[3]) : "r"(addr));
}
__device__ __forceinline__ void mma16816(float* c, const uint32_t* a, const uint32_t* b) {
    asm volatile(
        "mma.sync.aligned.m16n8k16.row.col.f32.f16.f16.f32 "
        "{%0,%1,%2,%3}, {%4,%5,%6,%7}, {%8,%9}, {%0,%1,%2,%3};"
        : "+f"(c[0]), "+f"(c[1]), "+f"(c[2]), "+f"(c[3])
        : "r"(a[0]), "r"(a[1]), "r"(a[2]), "r"(a[3]), "r"(b[0]), "r"(b[1]));
}

// ---------------------------------------------------------------------------
// 0) zero counters
// ---------------------------------------------------------------------------
__global__ void init_kernel() {
    if (threadIdx.x < NEXP) g_cnt[threadIdx.x] = 0;
}

// ---------------------------------------------------------------------------
// 1) gating: scores + routing + x fp16 hi/lo split (token space)
// ---------------------------------------------------------------------------
__global__ void gating_kernel(const float* __restrict__ x,
                              const float* __restrict__ Wg,
                              const float* __restrict__ bg) {
    int gw = (blockIdx.x * blockDim.x + threadIdx.x) >> 5;
    if (gw >= TOK) return;
    int lane = threadIdx.x & 31;
    const float* xr = x + (size_t)gw * DDIM;
    __half* xh = g_xh + (size_t)gw * DDIM;
    __half* xl = g_xl + (size_t)gw * DDIM;

    float s[NEXP];
#pragma unroll
    for (int e = 0; e < NEXP; e++) s[e] = 0.f;
#pragma unroll
    for (int i = 0; i < 16; i++) {
        int d = lane + i * 32;
        float xv = xr[d];
        const float* wr = Wg + d * NEXP;
#pragma unroll
        for (int e = 0; e < NEXP; e++) s[e] += xv * wr[e];
        __half h = __float2half_rn(xv);
        xh[d] = h;
        xl[d] = __float2half_rn(xv - __half2float(h));
    }
#pragma unroll
    for (int e = 0; e < NEXP; e++) {
#pragma unroll
        for (int o = 16; o > 0; o >>= 1)
            s[e] += __shfl_xor_sync(0xffffffffu, s[e], o);
    }
    if (lane == 0) {
#pragma unroll
        for (int e = 0; e < NEXP; e++) s[e] += bg[e];
        int i0 = 0; float v0 = s[0];
        for (int e = 1; e < NEXP; e++) if (s[e] > v0) { v0 = s[e]; i0 = e; }
        int i1 = -1; float v1 = -1e30f;
        for (int e = 0; e < NEXP; e++) if (e != i0 && s[e] > v1) { v1 = s[e]; i1 = e; }
        int j0 = 0; float u0 = s[0];
        for (int e = 1; e < NEXP; e++) if (s[e] < u0) { u0 = s[e]; j0 = e; }
        int j1 = -1; float u1 = 1e30f;
        for (int e = 0; e < NEXP; e++) if (e != j0 && s[e] < u1) { u1 = s[e]; j1 = e; }

        float et  = expf(v1 - v0);
        float wt0 = 1.f / (1.f + et);
        float wt1 = et * wt0;
        float eb  = expf(u0 - u1);
        float wb1 = 1.f / (1.f + eb);
        float wb0 = eb * wb1;

        int p;
        p = atomicAdd(&g_cnt[i0], 1);
        g_pairTok[i0 * TOK + p] = gw;
        g_tokPair[gw * 4 + 0] = i0 * TOK + p;  g_tokW[gw * 4 + 0] = wt0;
        p = atomicAdd(&g_cnt[i1], 1);
        g_pairTok[i1 * TOK + p] = gw;
        g_tokPair[gw * 4 + 1] = i1 * TOK + p;  g_tokW[gw * 4 + 1] = wt1;
        p = atomicAdd(&g_cnt[j0], 1);
        g_pairTok[j0 * TOK + p] = gw;
        g_tokPair[gw * 4 + 2] = j0 * TOK + p;  g_tokW[gw * 4 + 2] = wb0;
        p = atomicAdd(&g_cnt[j1], 1);
        g_pairTok[j1 * TOK + p] = gw;
        g_tokPair[gw * 4 + 3] = j1 * TOK + p;  g_tokW[gw * 4 + 3] = wb1;
    }
}

// ---------------------------------------------------------------------------
// 1b) weight prep: W[e][k][n] fp32 -> Wt[e][n][k] fp16 (transpose + round)
// ---------------------------------------------------------------------------
template <int WHICH>
__global__ void wconv_kernel(const float* __restrict__ W) {
    __shared__ float t[32][33];
    int e  = blockIdx.z;
    int kb = blockIdx.x * 32, nb = blockIdx.y * 32;
    const float* src = W + (size_t)e * DDIM * DDIM;
    int tx = threadIdx.x, ty = threadIdx.y;
#pragma unroll
    for (int r = ty; r < 32; r += 8)
        t[r][tx] = src[(size_t)(kb + r) * DDIM + nb + tx];
    __syncthreads();
    __half* T = (WHICH == 1) ? g_w1t : g_w2t;
#pragma unroll
    for (int r = ty; r < 32; r += 8) {
        float v = t[tx][r];  // = W[kb+tx][nb+r]
        T[((size_t)e * DDIM + (nb + r)) * DDIM + kb + tx] = __float2half_rn(v);
    }
}

// ---------------------------------------------------------------------------
// 2/4) fp16 2-term HMMA GEMM, cp.async 3-stage pipeline.
//      BM=128, BN=256, BK=32; 256 threads = 8 warps (2 x 4), warp tile 64x64.
//      WHICH=1: A = g_xh/g_xl gathered via pairTok; out g_h1 (fp16).
//      WHICH=2: A = g_ah/g_al pair-space (ln1 out); out g_h2 (fp16).
// ---------------------------------------------------------------------------
template <int WHICH>
__global__ void __launch_bounds__(256, 1) gemm_mma(const float* __restrict__ bias) {
    const int e   = blockIdx.z;
    const int cnt = g_cnt[e];
    const int m0  = blockIdx.y * BM;
    if (m0 >= cnt) return;
    const int n0  = blockIdx.x * BN;

    extern __shared__ char dsm[];
    const uint32_t sbase = smem_u32(dsm);

    const int tid  = threadIdx.x;
    const int wid  = tid >> 5;
    const int lane = tid & 31;

    const __half* wt = (WHICH == 1) ? g_w1t : g_w2t;

    // ---- loader precompute: 8 x 16B segments per thread per stage ----
    const __half* src[8];
    uint32_t dst[8];
#pragma unroll
    for (int j = 0; j < 8; j++) {
        int gid = tid + j * 256;
        if (gid < 1024) {                       // A (hi then lo)
            int mat = gid >> 9;
            int idx = gid & 511;
            int row = idx >> 2, ks = idx & 3;
            int rr = m0 + row; if (rr > cnt - 1) rr = cnt - 1;
            if (WHICH == 1) {
                int tokid = g_pairTok[e * TOK + rr];
                src[j] = (mat ? g_xl : g_xh) + (size_t)tokid * DDIM + ks * 8;
            } else {
                src[j] = (mat ? g_al : g_ah) + ((size_t)e * TOK + rr) * DDIM + ks * 8;
            }
            dst[j] = (mat ? AL_OFF : AH_OFF) + row * 80 + ks * 16;
        } else {                                // B (single fp16)
            int idx = gid - 1024;               // 0..1023
            int row = idx >> 2, ks = idx & 3;
            src[j] = wt + ((size_t)e * DDIM + n0 + row) * DDIM + ks * 8;
            dst[j] = B_OFF + row * 80 + ks * 16;
        }
    }

    auto issue = [&](int chunk, int s) {
        const int k0 = chunk * BK;
        const uint32_t sb = sbase + s * STAGE_B;
#pragma unroll
        for (int j = 0; j < 8; j++) cp16(sb + dst[j], src[j] + k0);
    };

    // warp layout: warp_m = wid>>2 (64 rows), warp_n = wid&3 (64 cols)
    const int warp_m = wid >> 2;
    const int warp_n = wid & 3;
    const int l15 = lane & 15;
    const uint32_t aoff = (uint32_t)((warp_m * 64 + l15) * 80 + (lane >> 4) * 16);
    const uint32_t boff = (uint32_t)((warp_n * 64 + (lane >> 4) * 8 + (lane & 7)) * 80 +
                                     ((lane >> 3) & 1) * 16);

    float acc[4][8][4];
#pragma unroll
    for (int mt = 0; mt < 4; mt++)
#pragma unroll
        for (int nt = 0; nt < 8; nt++)
#pragma unroll
            for (int q = 0; q < 4; q++) acc[mt][nt][q] = 0.f;

    issue(0, 0); CP_COMMIT();
    issue(1, 1); CP_COMMIT();

    for (int i = 0; i < NCHUNK; i++) {
        const int s = i % NSTAGE;
        CP_WAIT1();
        __syncthreads();
        if (i + 2 < NCHUNK) issue(i + 2, (i + 2) % NSTAGE);
        CP_COMMIT();

        const uint32_t sb = sbase + s * STAGE_B;
        const uint32_t aH = sb + AH_OFF + aoff;
        const uint32_t aL = sb + AL_OFF + aoff;
        const uint32_t bB = sb + B_OFF + boff;
#pragma unroll
        for (int k16 = 0; k16 < 2; k16++) {
            uint32_t bh[8][2];
#pragma unroll
            for (int p = 0; p < 4; p++) {
                uint32_t r4[4];
                ldsm4(r4, bB + p * 16 * 80 + k16 * 32);
                bh[2 * p][0] = r4[0]; bh[2 * p][1] = r4[1];
                bh[2 * p + 1][0] = r4[2]; bh[2 * p + 1][1] = r4[3];
            }
#pragma unroll
            for (int mt = 0; mt < 4; mt++) {
                uint32_t ah[4], al[4];
                ldsm4(ah, aH + mt * 16 * 80 + k16 * 32);
                ldsm4(al, aL + mt * 16 * 80 + k16 * 32);
#pragma unroll
                for (int nt = 0; nt < 8; nt++) {
                    mma16816(acc[mt][nt], ah, bh[nt]);
                    mma16816(acc[mt][nt], al, bh[nt]);
                }
            }
        }
    }

    // ---- epilogue: bias add + fp16 store ----
    const int groupid = lane >> 2;
    const int t4      = lane & 3;
    float2 bv[8];
#pragma unroll
    for (int nt = 0; nt < 8; nt++)
        bv[nt] = *(const float2*)(bias + (size_t)e * DDIM + n0 + warp_n * 64 + nt * 8 + t4 * 2);

    __half* OutB = (WHICH == 1) ? g_h1 : g_h2;
#pragma unroll
    for (int mt = 0; mt < 4; mt++) {
        int r0 = m0 + warp_m * 64 + mt * 16 + groupid;
        int r1 = r0 + 8;
        __half* p0 = OutB + ((size_t)e * TOK + r0) * DDIM + n0 + warp_n * 64 + t4 * 2;
        __half* p1 = OutB + ((size_t)e * TOK + r1) * DDIM + n0 + warp_n * 64 + t4 * 2;
#pragma unroll
        for (int nt = 0; nt < 8; nt++) {
            if (r0 < cnt)
                *(__half2*)(p0 + nt * 8) =
                    __floats2half2_rn(acc[mt][nt][0] + bv[nt].x, acc[mt][nt][1] + bv[nt].y);
            if (r1 < cnt)
                *(__half2*)(p1 + nt * 8) =
                    __floats2half2_rn(acc[mt][nt][2] + bv[nt].x, acc[mt][nt][3] + bv[nt].y);
        }
    }
}

// ---------------------------------------------------------------------------
// 3) LN1 + relu: reads g_h1 fp16, writes fp16 hi/lo into g_ah/g_al
// ---------------------------------------------------------------------------
__global__ void ln1_kernel(const float* __restrict__ w,
                           const float* __restrict__ b) {
    int gw = (blockIdx.x * blockDim.x + threadIdx.x) >> 5;
    int e   = gw >> 15;
    int pos = gw & (TOK - 1);
    if (pos >= g_cnt[e]) return;
    int lane = threadIdx.x & 31;
    const __half2* row = (const __half2*)(g_h1 + (size_t)gw * DDIM);

    float2 v[8];
    float s = 0.f;
#pragma unroll
    for (int i = 0; i < 8; i++) {
        v[i] = __half22float2(row[lane + i * 32]);
        s += v[i].x + v[i].y;
    }
#pragma unroll
    for (int o = 16; o > 0; o >>= 1) s += __shfl_xor_sync(0xffffffffu, s, o);
    float mu = s * (1.f / DDIM);

    float q = 0.f;
#pragma unroll
    for (int i = 0; i < 8; i++) {
        float dx = v[i].x - mu, dy = v[i].y - mu;
        q += dx * dx + dy * dy;
    }
#pragma unroll
    for (int o = 16; o > 0; o >>= 1) q += __shfl_xor_sync(0xffffffffu, q, o);
    float rstd = rsqrtf(q * (1.f / DDIM) + LN_EPS);

    const float* we = w + e * DDIM;
    const float* be = b + e * DDIM;
    __half* oh = g_ah + (size_t)gw * DDIM;
    __half* ol = g_al + (size_t)gw * DDIM;
#pragma unroll
    for (int i = 0; i < 8; i++) {
        int d = 2 * (lane + i * 32);
        float yx = fmaxf((v[i].x - mu) * rstd * we[d] + be[d], 0.f);
        float yy = fmaxf((v[i].y - mu) * rstd * we[d + 1] + be[d + 1], 0.f);
        __half hx = __float2half_rn(yx);
        __half hy = __float2half_rn(yy);
        *(__half2*)(oh + d) = __halves2half2(hx, hy);
        *(__half2*)(ol + d) = __floats2half2_rn(yx - __half2float(hx), yy - __half2float(hy));
    }
}

// ---------------------------------------------------------------------------
// 6) combine + fused LN2: warp per token; 4 fp16 rows of g_h2 (pre-LN)
// ---------------------------------------------------------------------------
__global__ void combine_kernel(const float* __restrict__ x,
                               const float* __restrict__ lnw,
                               const float* __restrict__ lnb,
                               float* __restrict__ out) {
    int gw   = (blockIdx.x * blockDim.x + threadIdx.x) >> 5;
    int lane = threadIdx.x & 31;
    const int t = gw;

    int   pr[4];
    float wt[4];
#pragma unroll
    for (int j = 0; j < 4; j++) {
        pr[j] = g_tokPair[t * 4 + j];
        wt[j] = g_tokW[t * 4 + j];
    }

    float2 v[4][8];
    float mu[4], rs[4];
#pragma unroll
    for (int r = 0; r < 4; r++) {
        const __half2* row = (const __half2*)(g_h2 + (size_t)pr[r] * DDIM);
        float s = 0.f;
#pragma unroll
        for (int i = 0; i < 8; i++) {
            v[r][i] = __half22float2(row[lane + i * 32]);
            s += v[r][i].x + v[r][i].y;
        }
#pragma unroll
        for (int o = 16; o > 0; o >>= 1) s += __shfl_xor_sync(0xffffffffu, s, o);
        mu[r] = s * (1.f / DDIM);
        float q = 0.f;
#pragma unroll
        for (int i = 0; i < 8; i++) {
            float dx = v[r][i].x - mu[r], dy = v[r][i].y - mu[r];
            q += dx * dx + dy * dy;
        }
#pragma unroll
        for (int o = 16; o > 0; o >>= 1) q += __shfl_xor_sync(0xffffffffu, q, o);
        rs[r] = rsqrtf(q * (1.f / DDIM) + LN_EPS);
    }

    const float* lw[4];
    const float* lb[4];
#pragma unroll
    for (int r = 0; r < 4; r++) {
        int e = pr[r] >> 15;           // / TOK
        lw[r] = lnw + (size_t)e * DDIM;
        lb[r] = lnb + (size_t)e * DDIM;
    }

    const float* xr = x + (size_t)t * DDIM;
    float* o_out = out + (size_t)t * DDIM;
    float* o_top = out + (size_t)BND + (size_t)t * DDIM;
    float* o_bot = out + 2 * (size_t)BND + (size_t)t * DDIM;

    float accd = 0.f;
#pragma unroll
    for (int i = 0; i < 8; i++) {
        int d = 2 * (lane + i * 32);
#pragma unroll
        for (int h = 0; h < 2; h++) {
            int dd = d + h;
            float va = h ? v[0][i].y : v[0][i].x;
            float vb = h ? v[1][i].y : v[1][i].x;
            float vc = h ? v[2][i].y : v[2][i].x;
            float vd = h ? v[3][i].y : v[3][i].x;
            float ya = (va - mu[0]) * rs[0] * lw[0][dd] + lb[0][dd];
            float yb = (vb - mu[1]) * rs[1] * lw[1][dd] + lb[1][dd];
            float yc = (vc - mu[2]) * rs[2] * lw[2][dd] + lb[2][dd];
            float yd = (vd - mu[3]) * rs[3] * lw[3][dd] + lb[3][dd];
            float top = wt[0] * ya + wt[1] * yb;
            float bot = wt[2] * yc + wt[3] * yd;
            o_top[dd] = top;
            o_bot[dd] = bot;
            o_out[dd] = top + xr[dd];
            float df = top - bot;
            accd += df * df;
        }
    }
#pragma unroll
    for (int o = 16; o > 0; o >>= 1) accd += __shfl_xor_sync(0xffffffffu, accd, o);

    __shared__ float red[8];
    if (lane == 0) red[threadIdx.x >> 5] = accd;
    __syncthreads();
    if (threadIdx.x == 0) {
        float ssum = 0.f;
        for (int i = 0; i < 8; i++) ssum += red[i];
        g_part[blockIdx.x] = ssum;
    }
}

// ---------------------------------------------------------------------------
// 7) loss
// ---------------------------------------------------------------------------
__global__ void loss_kernel(float* __restrict__ out) {
    int w = threadIdx.x >> 5, lane = threadIdx.x & 31;
    __shared__ float lred[8];
    float s = 0.f;
    for (int i = lane; i < 512; i += 32) s += g_part[w * 512 + i];
#pragma unroll
    for (int o = 16; o > 0; o >>= 1) s += __shfl_xor_sync(0xffffffffu, s, o);
    if (lane == 0) lred[w] = 1.f / (sqrtf(s) + 1e-8f);
    __syncthreads();
    if (threadIdx.x == 0) {
        float a = 0.f;
        for (int i = 0; i < 8; i++) a += lred[i];
        out[(size_t)3 * BND] = a * (1.f / 8.f);
    }
}

// ---------------------------------------------------------------------------
// launch
// ---------------------------------------------------------------------------
extern "C" void kernel_launch(void* const* d_in, const int* in_sizes, int n_in,
                              void* d_out, int out_size) {
    const float* x    = (const float*)d_in[0];
    const float* Wg   = (const float*)d_in[1];
    const float* bg   = (const float*)d_in[2];
    const float* W1   = (const float*)d_in[3];
    const float* b1   = (const float*)d_in[4];
    const float* ln1w = (const float*)d_in[5];
    const float* ln1b = (const float*)d_in[6];
    const float* W2   = (const float*)d_in[7];
    const float* b2   = (const float*)d_in[8];
    const float* ln2w = (const float*)d_in[9];
    const float* ln2b = (const float*)d_in[10];
    float* out = (float*)d_out;

    static int smem_set = 0;
    if (!smem_set) {
        cudaFuncSetAttribute(gemm_mma<1>, cudaFuncAttributeMaxDynamicSharedMemorySize, SMEM_DYN);
        cudaFuncSetAttribute(gemm_mma<2>, cudaFuncAttributeMaxDynamicSharedMemorySize, SMEM_DYN);
        smem_set = 1;
    }

    init_kernel<<<1, 32>>>();
    gating_kernel<<<TOK * 32 / 256, 256>>>(x, Wg, bg);

    dim3 wgrid(DDIM / 32, DDIM / 32, NEXP);
    wconv_kernel<1><<<wgrid, dim3(32, 8)>>>(W1);
    wconv_kernel<2><<<wgrid, dim3(32, 8)>>>(W2);

    dim3 ggrid(DDIM / BN, TOK / BM, NEXP);   // (2, 256, 8)
    gemm_mma<1><<<ggrid, 256, SMEM_DYN>>>(b1);
    ln1_kernel<<<NEXP * TOK * 32 / 256, 256>>>(ln1w, ln1b);
    gemm_mma<2><<<ggrid, 256, SMEM_DYN>>>(b2);
    combine_kernel<<<TOK * 32 / 256, 256>>>(x, ln2w, ln2b, out);
    loss_kernel<<<1, 256>>>(out);
}

// round 8
// speedup vs baseline: 3.9370x; 1.3485x over previous
#include <cuda_runtime.h>
#include <cuda_fp16.h>
#include <math.h>
#include <stdint.h>

// Problem constants
#define TOK   32768          // B*N = 8*4096
#define NEXP  8
#define DDIM  512
#define BND   16777216       // TOK * DDIM
#define LN_EPS 1e-5f

// GEMM tile config (pure fp16 operands, fp32 accum)
#define BM 128
#define BN 256
#define BK 32
#define NCHUNK (DDIM / BK)   // 16
// smem stage layout (bytes): rows padded to 40 fp16 = 80B (conflict-free ldsm)
#define A_OFF 0
#define B_OFF 10240
#define STAGE_B 30720
#define NSTAGE 3
#define SMEM_DYN (NSTAGE * STAGE_B)   // 92160

// ---------------------------------------------------------------------------
// Scratch (__device__ globals; no allocations allowed)
// ---------------------------------------------------------------------------
__device__ int   g_cnt[NEXP];
__device__ int   g_pairTok[NEXP * TOK];
__device__ int   g_tokPair[TOK * 4];
__device__ float g_tokW[TOK * 4];
__device__ __half g_h1[(size_t)NEXP * TOK * DDIM];   // GEMM1 out (pre-LN1), fp16
__device__ __half g_h2[(size_t)NEXP * TOK * DDIM];   // GEMM2 out (pre-LN2), fp16
__device__ float g_part[4096];
__device__ __half g_xh[(size_t)TOK * DDIM];          // x fp16 (token space)
__device__ __half g_ah[(size_t)NEXP * TOK * DDIM];   // ln1 out fp16 (pair space)
__device__ __half g_w1t[(size_t)NEXP * DDIM * DDIM]; // W1^T fp16
__device__ __half g_w2t[(size_t)NEXP * DDIM * DDIM]; // W2^T fp16

// ---------------------------------------------------------------------------
// Helpers
// ---------------------------------------------------------------------------
__device__ __forceinline__ uint32_t smem_u32(const void* p) {
    uint32_t a;
    asm("{ .reg .u64 t; cvta.to.shared.u64 t, %1; cvt.u32.u64 %0, t; }" : "=r"(a) : "l"(p));
    return a;
}
__device__ __forceinline__ void cp16(uint32_t dst, const void* src) {
    asm volatile("cp.async.cg.shared.global [%0], [%1], 16;" :: "r"(dst), "l"(src));
}
#define CP_COMMIT() asm volatile("cp.async.commit_group;" ::: "memory")
#define CP_WAIT1()  asm volatile("cp.async.wait_group 1;" ::: "memory")
__device__ __forceinline__ void ldsm4(uint32_t* r, uint32_t addr) {
    asm volatile("ldmatrix.sync.aligned.m8n8.x4.shared.b16 {%0,%1,%2,%3}, [%4];"
                 : "=r"(r[0]), "=r"(r[1]), "=r"(r[2]), "=r"(r[3]) : "r"(addr));
}
__device__ __forceinline__ void mma16816(float* c, const uint32_t* a, const uint32_t* b) {
    asm volatile(
        "mma.sync.aligned.m16n8k16.row.col.f32.f16.f16.f32 "
        "{%0,%1,%2,%3}, {%4,%5,%6,%7}, {%8,%9}, {%0,%1,%2,%3};"
        : "+f"(c[0]), "+f"(c[1]), "+f"(c[2]), "+f"(c[3])
        : "r"(a[0]), "r"(a[1]), "r"(a[2]), "r"(a[3]), "r"(b[0]), "r"(b[1]));
}

// ---------------------------------------------------------------------------
// 0) zero counters
// ---------------------------------------------------------------------------
__global__ void init_kernel() {
    if (threadIdx.x < NEXP) g_cnt[threadIdx.x] = 0;
}

// ---------------------------------------------------------------------------
// 1) gating: scores + routing + x fp16 round (token space)
// ---------------------------------------------------------------------------
__global__ void gating_kernel(const float* __restrict__ x,
                              const float* __restrict__ Wg,
                              const float* __restrict__ bg) {
    int gw = (blockIdx.x * blockDim.x + threadIdx.x) >> 5;
    if (gw >= TOK) return;
    int lane = threadIdx.x & 31;
    const float* xr = x + (size_t)gw * DDIM;
    __half* xh = g_xh + (size_t)gw * DDIM;

    float s[NEXP];
#pragma unroll
    for (int e = 0; e < NEXP; e++) s[e] = 0.f;
#pragma unroll
    for (int i = 0; i < 16; i++) {
        int d = lane + i * 32;
        float xv = xr[d];
        const float* wr = Wg + d * NEXP;
#pragma unroll
        for (int e = 0; e < NEXP; e++) s[e] += xv * wr[e];
        xh[d] = __float2half_rn(xv);
    }
#pragma unroll
    for (int e = 0; e < NEXP; e++) {
#pragma unroll
        for (int o = 16; o > 0; o >>= 1)
            s[e] += __shfl_xor_sync(0xffffffffu, s[e], o);
    }
    if (lane == 0) {
#pragma unroll
        for (int e = 0; e < NEXP; e++) s[e] += bg[e];
        int i0 = 0; float v0 = s[0];
        for (int e = 1; e < NEXP; e++) if (s[e] > v0) { v0 = s[e]; i0 = e; }
        int i1 = -1; float v1 = -1e30f;
        for (int e = 0; e < NEXP; e++) if (e != i0 && s[e] > v1) { v1 = s[e]; i1 = e; }
        int j0 = 0; float u0 = s[0];
        for (int e = 1; e < NEXP; e++) if (s[e] < u0) { u0 = s[e]; j0 = e; }
        int j1 = -1; float u1 = 1e30f;
        for (int e = 0; e < NEXP; e++) if (e != j0 && s[e] < u1) { u1 = s[e]; j1 = e; }

        float et  = expf(v1 - v0);
        float wt0 = 1.f / (1.f + et);
        float wt1 = et * wt0;
        float eb  = expf(u0 - u1);
        float wb1 = 1.f / (1.f + eb);
        float wb0 = eb * wb1;

        int p;
        p = atomicAdd(&g_cnt[i0], 1);
        g_pairTok[i0 * TOK + p] = gw;
        g_tokPair[gw * 4 + 0] = i0 * TOK + p;  g_tokW[gw * 4 + 0] = wt0;
        p = atomicAdd(&g_cnt[i1], 1);
        g_pairTok[i1 * TOK + p] = gw;
        g_tokPair[gw * 4 + 1] = i1 * TOK + p;  g_tokW[gw * 4 + 1] = wt1;
        p = atomicAdd(&g_cnt[j0], 1);
        g_pairTok[j0 * TOK + p] = gw;
        g_tokPair[gw * 4 + 2] = j0 * TOK + p;  g_tokW[gw * 4 + 2] = wb0;
        p = atomicAdd(&g_cnt[j1], 1);
        g_pairTok[j1 * TOK + p] = gw;
        g_tokPair[gw * 4 + 3] = j1 * TOK + p;  g_tokW[gw * 4 + 3] = wb1;
    }
}

// ---------------------------------------------------------------------------
// 1b) weight prep: W[e][k][n] fp32 -> Wt[e][n][k] fp16 (transpose + round)
// ---------------------------------------------------------------------------
template <int WHICH>
__global__ void wconv_kernel(const float* __restrict__ W) {
    __shared__ float t[32][33];
    int e  = blockIdx.z;
    int kb = blockIdx.x * 32, nb = blockIdx.y * 32;
    const float* src = W + (size_t)e * DDIM * DDIM;
    int tx = threadIdx.x, ty = threadIdx.y;
#pragma unroll
    for (int r = ty; r < 32; r += 8)
        t[r][tx] = src[(size_t)(kb + r) * DDIM + nb + tx];
    __syncthreads();
    __half* T = (WHICH == 1) ? g_w1t : g_w2t;
#pragma unroll
    for (int r = ty; r < 32; r += 8) {
        float v = t[tx][r];  // = W[kb+tx][nb+r]
        T[((size_t)e * DDIM + (nb + r)) * DDIM + kb + tx] = __float2half_rn(v);
    }
}

// ---------------------------------------------------------------------------
// 2/4) fp16 HMMA GEMM, cp.async 3-stage pipeline.
//      BM=128, BN=256, BK=32; 256 threads = 8 warps (2 x 4), warp tile 64x64.
//      WHICH=1: A = g_xh gathered via pairTok; out g_h1 (fp16).
//      WHICH=2: A = g_ah pair-space (ln1 out); out g_h2 (fp16).
// ---------------------------------------------------------------------------
template <int WHICH>
__global__ void __launch_bounds__(256, 1) gemm_mma(const float* __restrict__ bias) {
    const int e   = blockIdx.z;
    const int cnt = g_cnt[e];
    const int m0  = blockIdx.y * BM;
    if (m0 >= cnt) return;
    const int n0  = blockIdx.x * BN;

    extern __shared__ char dsm[];
    const uint32_t sbase = smem_u32(dsm);

    const int tid  = threadIdx.x;
    const int wid  = tid >> 5;
    const int lane = tid & 31;

    const __half* wt = (WHICH == 1) ? g_w1t : g_w2t;

    // ---- loader precompute: 6 x 16B segments per thread per stage ----
    const __half* src[6];
    uint32_t dst[6];
#pragma unroll
    for (int j = 0; j < 6; j++) {
        int gid = tid + j * 256;
        if (gid < 512) {                        // A: 128 rows x 4 segs
            int row = gid >> 2, ks = gid & 3;
            int rr = m0 + row; if (rr > cnt - 1) rr = cnt - 1;
            if (WHICH == 1) {
                int tokid = g_pairTok[e * TOK + rr];
                src[j] = g_xh + (size_t)tokid * DDIM + ks * 8;
            } else {
                src[j] = g_ah + ((size_t)e * TOK + rr) * DDIM + ks * 8;
            }
            dst[j] = A_OFF + row * 80 + ks * 16;
        } else {                                // B: 256 rows x 4 segs
            int idx = gid - 512;
            int row = idx >> 2, ks = idx & 3;
            src[j] = wt + ((size_t)e * DDIM + n0 + row) * DDIM + ks * 8;
            dst[j] = B_OFF + row * 80 + ks * 16;
        }
    }

    auto issue = [&](int chunk, int s) {
        const int k0 = chunk * BK;
        const uint32_t sb = sbase + s * STAGE_B;
#pragma unroll
        for (int j = 0; j < 6; j++) cp16(sb + dst[j], src[j] + k0);
    };

    // warp layout: warp_m = wid>>2 (64 rows), warp_n = wid&3 (64 cols)
    const int warp_m = wid >> 2;
    const int warp_n = wid & 3;
    const int l15 = lane & 15;
    const uint32_t aoff = (uint32_t)((warp_m * 64 + l15) * 80 + (lane >> 4) * 16);
    const uint32_t boff = (uint32_t)((warp_n * 64 + (lane >> 4) * 8 + (lane & 7)) * 80 +
                                     ((lane >> 3) & 1) * 16);

    float acc[4][8][4];
#pragma unroll
    for (int mt = 0; mt < 4; mt++)
#pragma unroll
        for (int nt = 0; nt < 8; nt++)
#pragma unroll
            for (int q = 0; q < 4; q++) acc[mt][nt][q] = 0.f;

    issue(0, 0); CP_COMMIT();
    issue(1, 1); CP_COMMIT();

    for (int i = 0; i < NCHUNK; i++) {
        const int s = i % NSTAGE;
        CP_WAIT1();
        __syncthreads();
        if (i + 2 < NCHUNK) issue(i + 2, (i + 2) % NSTAGE);
        CP_COMMIT();

        const uint32_t sb = sbase + s * STAGE_B;
        const uint32_t aA = sb + A_OFF + aoff;
        const uint32_t bB = sb + B_OFF + boff;
#pragma unroll
        for (int k16 = 0; k16 < 2; k16++) {
            uint32_t bh[8][2];
#pragma unroll
            for (int p = 0; p < 4; p++) {
                uint32_t r4[4];
                ldsm4(r4, bB + p * 16 * 80 + k16 * 32);
                bh[2 * p][0] = r4[0]; bh[2 * p][1] = r4[1];
                bh[2 * p + 1][0] = r4[2]; bh[2 * p + 1][1] = r4[3];
            }
#pragma unroll
            for (int mt = 0; mt < 4; mt++) {
                uint32_t ah[4];
                ldsm4(ah, aA + mt * 16 * 80 + k16 * 32);
#pragma unroll
                for (int nt = 0; nt < 8; nt++)
                    mma16816(acc[mt][nt], ah, bh[nt]);
            }
        }
    }

    // ---- epilogue: bias add + fp16 store ----
    const int groupid = lane >> 2;
    const int t4      = lane & 3;
    float2 bv[8];
#pragma unroll
    for (int nt = 0; nt < 8; nt++)
        bv[nt] = *(const float2*)(bias + (size_t)e * DDIM + n0 + warp_n * 64 + nt * 8 + t4 * 2);

    __half* OutB = (WHICH == 1) ? g_h1 : g_h2;
#pragma unroll
    for (int mt = 0; mt < 4; mt++) {
        int r0 = m0 + warp_m * 64 + mt * 16 + groupid;
        int r1 = r0 + 8;
        __half* p0 = OutB + ((size_t)e * TOK + r0) * DDIM + n0 + warp_n * 64 + t4 * 2;
        __half* p1 = OutB + ((size_t)e * TOK + r1) * DDIM + n0 + warp_n * 64 + t4 * 2;
#pragma unroll
        for (int nt = 0; nt < 8; nt++) {
            if (r0 < cnt)
                *(__half2*)(p0 + nt * 8) =
                    __floats2half2_rn(acc[mt][nt][0] + bv[nt].x, acc[mt][nt][1] + bv[nt].y);
            if (r1 < cnt)
                *(__half2*)(p1 + nt * 8) =
                    __floats2half2_rn(acc[mt][nt][2] + bv[nt].x, acc[mt][nt][3] + bv[nt].y);
        }
    }
}

// ---------------------------------------------------------------------------
// 3) LN1 + relu: reads g_h1 fp16, writes fp16 into g_ah
// ---------------------------------------------------------------------------
__global__ void ln1_kernel(const float* __restrict__ w,
                           const float* __restrict__ b) {
    int gw = (blockIdx.x * blockDim.x + threadIdx.x) >> 5;
    int e   = gw >> 15;
    int pos = gw & (TOK - 1);
    if (pos >= g_cnt[e]) return;
    int lane = threadIdx.x & 31;
    const __half2* row = (const __half2*)(g_h1 + (size_t)gw * DDIM);

    float2 v[8];
    float s = 0.f;
#pragma unroll
    for (int i = 0; i < 8; i++) {
        v[i] = __half22float2(row[lane + i * 32]);
        s += v[i].x + v[i].y;
    }
#pragma unroll
    for (int o = 16; o > 0; o >>= 1) s += __shfl_xor_sync(0xffffffffu, s, o);
    float mu = s * (1.f / DDIM);

    float q = 0.f;
#pragma unroll
    for (int i = 0; i < 8; i++) {
        float dx = v[i].x - mu, dy = v[i].y - mu;
        q += dx * dx + dy * dy;
    }
#pragma unroll
    for (int o = 16; o > 0; o >>= 1) q += __shfl_xor_sync(0xffffffffu, q, o);
    float rstd = rsqrtf(q * (1.f / DDIM) + LN_EPS);

    const float* we = w + e * DDIM;
    const float* be = b + e * DDIM;
    __half* oh = g_ah + (size_t)gw * DDIM;
#pragma unroll
    for (int i = 0; i < 8; i++) {
        int d = 2 * (lane + i * 32);
        float yx = fmaxf((v[i].x - mu) * rstd * we[d] + be[d], 0.f);
        float yy = fmaxf((v[i].y - mu) * rstd * we[d + 1] + be[d + 1], 0.f);
        *(__half2*)(oh + d) = __floats2half2_rn(yx, yy);
    }
}

// ---------------------------------------------------------------------------
// 6) combine + fused LN2: warp per token; 4 fp16 rows of g_h2 (pre-LN)
// ---------------------------------------------------------------------------
__global__ void combine_kernel(const float* __restrict__ x,
                               const float* __restrict__ lnw,
                               const float* __restrict__ lnb,
                               float* __restrict__ out) {
    int gw   = (blockIdx.x * blockDim.x + threadIdx.x) >> 5;
    int lane = threadIdx.x & 31;
    const int t = gw;

    int   pr[4];
    float wt[4];
#pragma unroll
    for (int j = 0; j < 4; j++) {
        pr[j] = g_tokPair[t * 4 + j];
        wt[j] = g_tokW[t * 4 + j];
    }

    float2 v[4][8];
    float mu[4], rs[4];
#pragma unroll
    for (int r = 0; r < 4; r++) {
        const __half2* row = (const __half2*)(g_h2 + (size_t)pr[r] * DDIM);
        float s = 0.f;
#pragma unroll
        for (int i = 0; i < 8; i++) {
            v[r][i] = __half22float2(row[lane + i * 32]);
            s += v[r][i].x + v[r][i].y;
        }
#pragma unroll
        for (int o = 16; o > 0; o >>= 1) s += __shfl_xor_sync(0xffffffffu, s, o);
        mu[r] = s * (1.f / DDIM);
        float q = 0.f;
#pragma unroll
        for (int i = 0; i < 8; i++) {
            float dx = v[r][i].x - mu[r], dy = v[r][i].y - mu[r];
            q += dx * dx + dy * dy;
        }
#pragma unroll
        for (int o = 16; o > 0; o >>= 1) q += __shfl_xor_sync(0xffffffffu, q, o);
        rs[r] = rsqrtf(q * (1.f / DDIM) + LN_EPS);
    }

    const float* lw[4];
    const float* lb[4];
#pragma unroll
    for (int r = 0; r < 4; r++) {
        int e = pr[r] >> 15;           // / TOK
        lw[r] = lnw + (size_t)e * DDIM;
        lb[r] = lnb + (size_t)e * DDIM;
    }

    const float* xr = x + (size_t)t * DDIM;
    float* o_out = out + (size_t)t * DDIM;
    float* o_top = out + (size_t)BND + (size_t)t * DDIM;
    float* o_bot = out + 2 * (size_t)BND + (size_t)t * DDIM;

    float accd = 0.f;
#pragma unroll
    for (int i = 0; i < 8; i++) {
        int d = 2 * (lane + i * 32);
#pragma unroll
        for (int h = 0; h < 2; h++) {
            int dd = d + h;
            float va = h ? v[0][i].y : v[0][i].x;
            float vb = h ? v[1][i].y : v[1][i].x;
            float vc = h ? v[2][i].y : v[2][i].x;
            float vd = h ? v[3][i].y : v[3][i].x;
            float ya = (va - mu[0]) * rs[0] * lw[0][dd] + lb[0][dd];
            float yb = (vb - mu[1]) * rs[1] * lw[1][dd] + lb[1][dd];
            float yc = (vc - mu[2]) * rs[2] * lw[2][dd] + lb[2][dd];
            float yd = (vd - mu[3]) * rs[3] * lw[3][dd] + lb[3][dd];
            float top = wt[0] * ya + wt[1] * yb;
            float bot = wt[2] * yc + wt[3] * yd;
            o_top[dd] = top;
            o_bot[dd] = bot;
            o_out[dd] = top + xr[dd];
            float df = top - bot;
            accd += df * df;
        }
    }
#pragma unroll
    for (int o = 16; o > 0; o >>= 1) accd += __shfl_xor_sync(0xffffffffu, accd, o);

    __shared__ float red[8];
    if (lane == 0) red[threadIdx.x >> 5] = accd;
    __syncthreads();
    if (threadIdx.x == 0) {
        float ssum = 0.f;
        for (int i = 0; i < 8; i++) ssum += red[i];
        g_part[blockIdx.x] = ssum;
    }
}

// ---------------------------------------------------------------------------
// 7) loss
// ---------------------------------------------------------------------------
__global__ void loss_kernel(float* __restrict__ out) {
    int w = threadIdx.x >> 5, lane = threadIdx.x & 31;
    __shared__ float lred[8];
    float s = 0.f;
    for (int i = lane; i < 512; i += 32) s += g_part[w * 512 + i];
#pragma unroll
    for (int o = 16; o > 0; o >>= 1) s += __shfl_xor_sync(0xffffffffu, s, o);
    if (lane == 0) lred[w] = 1.f / (sqrtf(s) + 1e-8f);
    __syncthreads();
    if (threadIdx.x == 0) {
        float a = 0.f;
        for (int i = 0; i < 8; i++) a += lred[i];
        out[(size_t)3 * BND] = a * (1.f / 8.f);
    }
}

// ---------------------------------------------------------------------------
// launch
// ---------------------------------------------------------------------------
extern "C" void kernel_launch(void* const* d_in, const int* in_sizes, int n_in,
                              void* d_out, int out_size) {
    const float* x    = (const float*)d_in[0];
    const float* Wg   = (const float*)d_in[1];
    const float* bg   = (const float*)d_in[2];
    const float* W1   = (const float*)d_in[3];
    const float* b1   = (const float*)d_in[4];
    const float* ln1w = (const float*)d_in[5];
    const float* ln1b = (const float*)d_in[6];
    const float* W2   = (const float*)d_in[7];
    const float* b2   = (const float*)d_in[8];
    const float* ln2w = (const float*)d_in[9];
    const float* ln2b = (const float*)d_in[10];
    float* out = (float*)d_out;

    static int smem_set = 0;
    if (!smem_set) {
        cudaFuncSetAttribute(gemm_mma<1>, cudaFuncAttributeMaxDynamicSharedMemorySize, SMEM_DYN);
        cudaFuncSetAttribute(gemm_mma<2>, cudaFuncAttributeMaxDynamicSharedMemorySize, SMEM_DYN);
        smem_set = 1;
    }

    init_kernel<<<1, 32>>>();
    gating_kernel<<<TOK * 32 / 256, 256>>>(x, Wg, bg);

    dim3 wgrid(DDIM / 32, DDIM / 32, NEXP);
    wconv_kernel<1><<<wgrid, dim3(32, 8)>>>(W1);
    wconv_kernel<2><<<wgrid, dim3(32, 8)>>>(W2);

    dim3 ggrid(DDIM / BN, TOK / BM, NEXP);   // (2, 256, 8)
    gemm_mma<1><<<ggrid, 256, SMEM_DYN>>>(b1);
    ln1_kernel<<<NEXP * TOK * 32 / 256, 256>>>(ln1w, ln1b);
    gemm_mma<2><<<ggrid, 256, SMEM_DYN>>>(b2);
    combine_kernel<<<TOK * 32 / 256, 256>>>(x, ln2w, ln2b, out);
    loss_kernel<<<1, 256>>>(out);
}